// round 2
// baseline (speedup 1.0000x reference)
#include <cuda_runtime.h>
#include <cuda_bf16.h>

// Problem constants: x [B, C, L], 32 groups, full attention over L.
#define BDIM 8
#define CDIM 512
#define LDIM 2048
#define NGRP 32
#define CPG  (CDIM / NGRP)   // 16
#define GN_EPS 1e-5f

// ---------------------------------------------------------------------------
// Scratch (no allocations allowed): one big __device__ array.
// layout (floats):
//   h : [B, C, L]      offset 0
//   q : [B, L, C]      offset 1*SZ
//   k : [B, L, C]      offset 2*SZ
//   v : [B, L, C]      offset 3*SZ
//   a : [B, L, C]      offset 4*SZ
//   s : [B, L, L]      offset 5*SZ
// ---------------------------------------------------------------------------
#define SZ   ((size_t)BDIM * CDIM * LDIM)          // 8,388,608
#define SSZ  ((size_t)BDIM * LDIM * LDIM)          // 33,554,432
__device__ float g_scratch[5 * SZ + SSZ];

// ---------------------------------------------------------------------------
// Warp / block reductions
// ---------------------------------------------------------------------------
__device__ __forceinline__ float warp_sum(float v) {
#pragma unroll
    for (int o = 16; o > 0; o >>= 1) v += __shfl_xor_sync(0xFFFFFFFFu, v, o);
    return v;
}
__device__ __forceinline__ float warp_max(float v) {
#pragma unroll
    for (int o = 16; o > 0; o >>= 1) v = fmaxf(v, __shfl_xor_sync(0xFFFFFFFFu, v, o));
    return v;
}

// ---------------------------------------------------------------------------
// GroupNorm: one block per (b, g). Reduce over CPG*L = 32768 elems, then
// normalize + affine, writing h in the same [B, C, L] layout (coalesced).
// ---------------------------------------------------------------------------
__global__ __launch_bounds__(256)
void gn_kernel(const float* __restrict__ x, const float* __restrict__ gamma,
               const float* __restrict__ beta, float* __restrict__ h) {
    const int b = blockIdx.x / NGRP;
    const int g = blockIdx.x % NGRP;
    const size_t base = ((size_t)b * CDIM + (size_t)g * CPG) * LDIM;
    const float4* xp = reinterpret_cast<const float4*>(x + base);
    float4* hp = reinterpret_cast<float4*>(h + base);

    const int n4 = CPG * LDIM / 4;  // 8192
    float s = 0.f, ss = 0.f;
    for (int i = threadIdx.x; i < n4; i += 256) {
        float4 t = xp[i];
        s  += t.x + t.y + t.z + t.w;
        ss += t.x * t.x + t.y * t.y + t.z * t.z + t.w * t.w;
    }
    __shared__ float sh1[8], sh2[8];
    int lane = threadIdx.x & 31, wid = threadIdx.x >> 5;
    s = warp_sum(s); ss = warp_sum(ss);
    if (lane == 0) { sh1[wid] = s; sh2[wid] = ss; }
    __syncthreads();
    if (wid == 0) {
        s  = (lane < 8) ? sh1[lane] : 0.f;
        ss = (lane < 8) ? sh2[lane] : 0.f;
        s = warp_sum(s); ss = warp_sum(ss);
        if (lane == 0) { sh1[0] = s; sh2[0] = ss; }
    }
    __syncthreads();
    const float inv_n = 1.f / (float)(CPG * LDIM);
    const float mean = sh1[0] * inv_n;
    const float var  = sh2[0] * inv_n - mean * mean;
    const float rstd = rsqrtf(var + GN_EPS);

    const int f4_per_ch = LDIM / 4;  // 512
    for (int i = threadIdx.x; i < n4; i += 256) {
        int c = i / f4_per_ch;                      // channel within group
        float sc = gamma[g * CPG + c] * rstd;
        float sb = beta[g * CPG + c] - mean * sc;
        float4 t = xp[i];
        t.x = t.x * sc + sb; t.y = t.y * sc + sb;
        t.z = t.z * sc + sb; t.w = t.w * sc + sb;
        hp[i] = t;
    }
}

// ---------------------------------------------------------------------------
// Generic fp32 GEMM, 128x128 block tile, K-tile 8, 8x8 per thread.
//   D[m, n] = sum_k A[m, k] * B[k, n]   (+ epilogue)
// A_KM : A stored as [K, M] (element (m,k) at k*lda + m); else [M, K]
// B_NK : B stored as [N, K] (element (k,n) at n*ldb + k); else [K, N]
// EPI  : 0 = none; 1 = +bias[n]; 2 = *alpha; 3 = +bias[m] + resid[m*ldc+n]
// blockIdx.z = batch; per-batch strides sA, sB, sD (resid uses sD).
// ---------------------------------------------------------------------------
template<bool A_KM, bool B_NK, int EPI>
__global__ __launch_bounds__(256)
void gemm_f32(const float* __restrict__ A, const float* __restrict__ B,
              float* __restrict__ D, int K, int lda, int ldb, int ldc,
              long long sA, long long sB, long long sD,
              const float* __restrict__ bias, float alpha,
              const float* __restrict__ resid) {
    __shared__ float As[8][128];
    __shared__ float Bs[8][128];

    const int tid = threadIdx.x;
    const int tx = tid & 15;        // 0..15 -> n sub-tile
    const int ty = tid >> 4;        // 0..15 -> m sub-tile
    const int m0 = blockIdx.y * 128;
    const int n0 = blockIdx.x * 128;
    const int b  = blockIdx.z;

    A += (long long)b * sA;
    B += (long long)b * sB;
    D += (long long)b * sD;
    if (EPI == 3) resid += (long long)b * sD;

    float acc[8][8];
#pragma unroll
    for (int i = 0; i < 8; i++)
#pragma unroll
        for (int j = 0; j < 8; j++) acc[i][j] = 0.f;

    for (int k0 = 0; k0 < K; k0 += 8) {
        // ---- load A tile -> As[k][m]
        if (A_KM) {
            int k = tid >> 5, m = (tid & 31) * 4;
            float4 t = *reinterpret_cast<const float4*>(
                &A[(long long)(k0 + k) * lda + m0 + m]);
            *reinterpret_cast<float4*>(&As[k][m]) = t;
        } else {
            int m = tid >> 1, k = (tid & 1) * 4;
            float4 t = *reinterpret_cast<const float4*>(
                &A[(long long)(m0 + m) * lda + k0 + k]);
            As[k + 0][m] = t.x; As[k + 1][m] = t.y;
            As[k + 2][m] = t.z; As[k + 3][m] = t.w;
        }
        // ---- load B tile -> Bs[k][n]
        if (B_NK) {
            int n = tid >> 1, k = (tid & 1) * 4;
            float4 t = *reinterpret_cast<const float4*>(
                &B[(long long)(n0 + n) * ldb + k0 + k]);
            Bs[k + 0][n] = t.x; Bs[k + 1][n] = t.y;
            Bs[k + 2][n] = t.z; Bs[k + 3][n] = t.w;
        } else {
            int k = tid >> 5, n = (tid & 31) * 4;
            float4 t = *reinterpret_cast<const float4*>(
                &B[(long long)(k0 + k) * ldb + n0 + n]);
            *reinterpret_cast<float4*>(&Bs[k][n]) = t;
        }
        __syncthreads();

#pragma unroll
        for (int k = 0; k < 8; k++) {
            float a[8], bb[8];
#pragma unroll
            for (int i = 0; i < 8; i++) a[i] = As[k][ty * 8 + i];
#pragma unroll
            for (int j = 0; j < 8; j++) bb[j] = Bs[k][tx * 8 + j];
#pragma unroll
            for (int i = 0; i < 8; i++)
#pragma unroll
                for (int j = 0; j < 8; j++) acc[i][j] = fmaf(a[i], bb[j], acc[i][j]);
        }
        __syncthreads();
    }

    // ---- epilogue
#pragma unroll
    for (int i = 0; i < 8; i++) {
        const int m = m0 + ty * 8 + i;
        float bm = 0.f;
        if (EPI == 3) bm = bias[m];
#pragma unroll
        for (int j = 0; j < 8; j += 4) {
            const int n = n0 + tx * 8 + j;
            float4 r;
            r.x = acc[i][j + 0]; r.y = acc[i][j + 1];
            r.z = acc[i][j + 2]; r.w = acc[i][j + 3];
            if (EPI == 1) {
                r.x += bias[n + 0]; r.y += bias[n + 1];
                r.z += bias[n + 2]; r.w += bias[n + 3];
            } else if (EPI == 2) {
                r.x *= alpha; r.y *= alpha; r.z *= alpha; r.w *= alpha;
            } else if (EPI == 3) {
                const float4 xr = *reinterpret_cast<const float4*>(
                    &resid[(long long)m * ldc + n]);
                r.x += bm + xr.x; r.y += bm + xr.y;
                r.z += bm + xr.z; r.w += bm + xr.w;
            }
            *reinterpret_cast<float4*>(&D[(long long)m * ldc + n]) = r;
        }
    }
}

// ---------------------------------------------------------------------------
// Row softmax over L=2048; one block (256 threads) per row, 8 elems/thread.
// ---------------------------------------------------------------------------
__global__ __launch_bounds__(256)
void softmax_kernel(float* __restrict__ S) {
    float4* row = reinterpret_cast<float4*>(S + (size_t)blockIdx.x * LDIM);
    const int t = threadIdx.x;
    float4 v0 = row[t];
    float4 v1 = row[t + 256];

    float m = fmaxf(fmaxf(fmaxf(v0.x, v0.y), fmaxf(v0.z, v0.w)),
                    fmaxf(fmaxf(v1.x, v1.y), fmaxf(v1.z, v1.w)));
    __shared__ float sh[8];
    int lane = t & 31, wid = t >> 5;
    m = warp_max(m);
    if (lane == 0) sh[wid] = m;
    __syncthreads();
    if (wid == 0) {
        float mm = (lane < 8) ? sh[lane] : -3.4e38f;
        mm = warp_max(mm);
        if (lane == 0) sh[0] = mm;
    }
    __syncthreads();
    m = sh[0];
    __syncthreads();

    v0.x = __expf(v0.x - m); v0.y = __expf(v0.y - m);
    v0.z = __expf(v0.z - m); v0.w = __expf(v0.w - m);
    v1.x = __expf(v1.x - m); v1.y = __expf(v1.y - m);
    v1.z = __expf(v1.z - m); v1.w = __expf(v1.w - m);

    float s = v0.x + v0.y + v0.z + v0.w + v1.x + v1.y + v1.z + v1.w;
    s = warp_sum(s);
    if (lane == 0) sh[wid] = s;
    __syncthreads();
    if (wid == 0) {
        float t2 = (lane < 8) ? sh[lane] : 0.f;
        t2 = warp_sum(t2);
        if (lane == 0) sh[0] = t2;
    }
    __syncthreads();
    const float inv = 1.f / sh[0];

    v0.x *= inv; v0.y *= inv; v0.z *= inv; v0.w *= inv;
    v1.x *= inv; v1.y *= inv; v1.z *= inv; v1.w *= inv;
    row[t] = v0;
    row[t + 256] = v1;
}

// ---------------------------------------------------------------------------
// Launch: groupnorm -> QKV GEMMs -> scores -> softmax -> PV -> O-proj+residual
// ---------------------------------------------------------------------------
extern "C" void kernel_launch(void* const* d_in, const int* in_sizes, int n_in,
                              void* d_out, int out_size) {
    const float* x   = (const float*)d_in[0];
    const float* gns = (const float*)d_in[1];
    const float* gnb = (const float*)d_in[2];
    const float* wq  = (const float*)d_in[3];
    const float* bq  = (const float*)d_in[4];
    const float* wk  = (const float*)d_in[5];
    const float* bk  = (const float*)d_in[6];
    const float* wv  = (const float*)d_in[7];
    const float* bv  = (const float*)d_in[8];
    const float* wo  = (const float*)d_in[9];
    const float* bo  = (const float*)d_in[10];
    float* out = (float*)d_out;

    float* scratch = nullptr;
    cudaGetSymbolAddress((void**)&scratch, g_scratch);
    float* h = scratch;
    float* q = scratch + 1 * SZ;
    float* k = scratch + 2 * SZ;
    float* v = scratch + 3 * SZ;
    float* a = scratch + 4 * SZ;
    float* s = scratch + 5 * SZ;

    const float attn_scale = 0.044194173824159216f;  // 512^-0.5

    // 1) GroupNorm: h [B, C, L]
    gn_kernel<<<BDIM * NGRP, 256>>>(x, gns, gnb, h);

    // 2) QKV: q[b,l,o] = sum_c h[b,c,l] * w[o,c] + b[o]
    //    M=L, N=C, K=C.  A = h (K-major: [C, L]); B = w ([N, K]).
    {
        dim3 grid(CDIM / 128, LDIM / 128, BDIM);
        gemm_f32<true, true, 1><<<grid, 256>>>(h, wq, q, CDIM, LDIM, CDIM, CDIM,
            (long long)CDIM * LDIM, 0, (long long)LDIM * CDIM, bq, 0.f, nullptr);
        gemm_f32<true, true, 1><<<grid, 256>>>(h, wk, k, CDIM, LDIM, CDIM, CDIM,
            (long long)CDIM * LDIM, 0, (long long)LDIM * CDIM, bk, 0.f, nullptr);
        gemm_f32<true, true, 1><<<grid, 256>>>(h, wv, v, CDIM, LDIM, CDIM, CDIM,
            (long long)CDIM * LDIM, 0, (long long)LDIM * CDIM, bv, 0.f, nullptr);
    }

    // 3) Scores: s[b,i,j] = scale * sum_c q[b,i,c] * k[b,j,c]
    //    M=L, N=L, K=C.  A = q ([M,K]); B = k ([N,K]).
    {
        dim3 grid(LDIM / 128, LDIM / 128, BDIM);
        gemm_f32<false, true, 2><<<grid, 256>>>(q, k, s, CDIM, CDIM, CDIM, LDIM,
            (long long)LDIM * CDIM, (long long)LDIM * CDIM,
            (long long)LDIM * LDIM, nullptr, attn_scale, nullptr);
    }

    // 4) Row softmax over j
    softmax_kernel<<<BDIM * LDIM, 256>>>(s);

    // 5) a[b,i,c] = sum_j p[b,i,j] * v[b,j,c]
    //    M=L, N=C, K=L.  A = p ([M,K]); B = v ([K,N]).
    {
        dim3 grid(CDIM / 128, LDIM / 128, BDIM);
        gemm_f32<false, false, 0><<<grid, 256>>>(s, v, a, LDIM, LDIM, CDIM, CDIM,
            (long long)LDIM * LDIM, (long long)LDIM * CDIM,
            (long long)LDIM * CDIM, nullptr, 0.f, nullptr);
    }

    // 6) out[b,o,l] = sum_c wo[o,c] * a[b,l,c] + bo[o] + x[b,o,l]
    //    M=C, N=L, K=C.  A = wo ([M,K], unbatched); B = a ([N,K]).
    {
        dim3 grid(LDIM / 128, CDIM / 128, BDIM);
        gemm_f32<false, true, 3><<<grid, 256>>>(wo, a, out, CDIM, CDIM, CDIM, LDIM,
            0, (long long)LDIM * CDIM, (long long)CDIM * LDIM, bo, 0.f, x);
    }
}

// round 4
// speedup vs baseline: 2.4738x; 2.4738x over previous
#include <cuda_runtime.h>
#include <cuda_bf16.h>
#include <cstdint>

// Problem: x [B=8, C=512, L=2048], GroupNorm(32) -> QKV -> attention -> O-proj + residual.
#define BDIM 8
#define CDIM 512
#define LDIM 2048
#define NGRP 32
#define CPG  (CDIM / NGRP)   // 16
#define GN_EPS 1e-5f

#define STRIDE_CL ((long long)CDIM * LDIM)
#define STRIDE_LL ((long long)LDIM * LDIM)

// Scratch: ht [B,L,C] | q [B,L,C] | k [B,L,C] | vT [B,C,L] | a [B,L,C] | s [B,L,L]
#define SZ   ((size_t)BDIM * CDIM * LDIM)
#define SSZ  ((size_t)BDIM * LDIM * LDIM)
__device__ __align__(256) float g_scratch[5 * SZ + SSZ];

// ---------------------------------------------------------------------------
__device__ __forceinline__ float warp_sum(float v) {
#pragma unroll
    for (int o = 16; o > 0; o >>= 1) v += __shfl_xor_sync(0xFFFFFFFFu, v, o);
    return v;
}
__device__ __forceinline__ float warp_max(float v) {
#pragma unroll
    for (int o = 16; o > 0; o >>= 1) v = fmaxf(v, __shfl_xor_sync(0xFFFFFFFFu, v, o));
    return v;
}
__device__ __forceinline__ float to_tf32(float x) {
    uint32_t r;
    asm("cvt.rna.tf32.f32 %0, %1;" : "=r"(r) : "f"(x));
    return __uint_as_float(r);
}
// portable tensor-core MMA (sm_80+): D[16x8] += A[16x8] * B[8x8]
__device__ __forceinline__ void mma_tf32(float* c, const uint32_t* a, const uint32_t* b) {
    asm volatile(
        "mma.sync.aligned.m16n8k8.row.col.f32.tf32.tf32.f32 "
        "{%0,%1,%2,%3}, {%4,%5,%6,%7}, {%8,%9}, {%0,%1,%2,%3};"
        : "+f"(c[0]), "+f"(c[1]), "+f"(c[2]), "+f"(c[3])
        : "r"(a[0]), "r"(a[1]), "r"(a[2]), "r"(a[3]), "r"(b[0]), "r"(b[1]));
}

// ============================================================================
// GroupNorm fused with transpose: x [B,C,L] -> ht [B,L,C]
// ============================================================================
__global__ __launch_bounds__(256)
void gn_t_kernel(const float* __restrict__ x, const float* __restrict__ gamma,
                 const float* __restrict__ beta, float* __restrict__ ht) {
    const int b = blockIdx.x / NGRP;
    const int g = blockIdx.x % NGRP;
    const size_t base = ((size_t)b * CDIM + (size_t)g * CPG) * LDIM;
    const float4* xp = reinterpret_cast<const float4*>(x + base);

    const int n4 = CPG * LDIM / 4;  // 8192
    float s = 0.f, ss = 0.f;
    for (int i = threadIdx.x; i < n4; i += 256) {
        float4 t = xp[i];
        s  += t.x + t.y + t.z + t.w;
        ss += t.x * t.x + t.y * t.y + t.z * t.z + t.w * t.w;
    }
    __shared__ float sh1[8], sh2[8];
    __shared__ float scg[CPG], sbg[CPG];
    int lane = threadIdx.x & 31, wid = threadIdx.x >> 5;
    s = warp_sum(s); ss = warp_sum(ss);
    if (lane == 0) { sh1[wid] = s; sh2[wid] = ss; }
    __syncthreads();
    if (wid == 0) {
        s  = (lane < 8) ? sh1[lane] : 0.f;
        ss = (lane < 8) ? sh2[lane] : 0.f;
        s = warp_sum(s); ss = warp_sum(ss);
        if (lane == 0) { sh1[0] = s; sh2[0] = ss; }
    }
    __syncthreads();
    const float inv_n = 1.f / (float)(CPG * LDIM);
    const float mean = sh1[0] * inv_n;
    const float var  = sh2[0] * inv_n - mean * mean;
    const float rstd = rsqrtf(var + GN_EPS);
    if (threadIdx.x < CPG) {
        float sc = gamma[g * CPG + threadIdx.x] * rstd;
        scg[threadIdx.x] = sc;
        sbg[threadIdx.x] = beta[g * CPG + threadIdx.x] - mean * sc;
    }
    __syncthreads();

    __shared__ float tile[CPG][133];
    for (int l0 = 0; l0 < LDIM; l0 += 128) {
        for (int it = threadIdx.x; it < 512; it += 256) {
            int c  = it >> 5;
            int l4 = (it & 31) * 4;
            float4 t = *reinterpret_cast<const float4*>(&x[base + (size_t)c * LDIM + l0 + l4]);
            float sc = scg[c], sb = sbg[c];
            tile[c][l4 + 0] = t.x * sc + sb;
            tile[c][l4 + 1] = t.y * sc + sb;
            tile[c][l4 + 2] = t.z * sc + sb;
            tile[c][l4 + 3] = t.w * sc + sb;
        }
        __syncthreads();
        for (int it = threadIdx.x; it < 512; it += 256) {
            int l  = it >> 2;
            int c4 = (it & 3) * 4;
            float4 o;
            o.x = tile[c4 + 0][l]; o.y = tile[c4 + 1][l];
            o.z = tile[c4 + 2][l]; o.w = tile[c4 + 3][l];
            *reinterpret_cast<float4*>(
                &ht[((size_t)b * LDIM + l0 + l) * CDIM + g * CPG + c4]) = o;
        }
        __syncthreads();
    }
}

// ============================================================================
// Tensor-core tf32 GEMM: D[m,n] = sum_k A[m,k]*B[n,k]  (A:[M,K], B:[N,K])
// CTA: 256 threads, 128x128 tile. Warp grid 2(m) x 4(n); warp tile 64x32.
// K-chunk 32, double-buffered SMEM (pitch 36 floats), register prefetch.
// EPI: 0=none 1=+bias[n] 2=transposed D[n*ldc+m]+bias[n] 3=*alpha
//      4=+bias[m]+resid[m*ldc+n]
// ============================================================================
#define PITCH 36
#define TILE_FLOATS (128 * PITCH)            // 4608 per operand
#define BUF_FLOATS  (2 * TILE_FLOATS)        // A + B per stage
#define GEMM_SMEM   (2 * BUF_FLOATS * 4)     // 73728 bytes

template<int EPI>
__global__ __launch_bounds__(256)
void gemm_mma(const float* __restrict__ A, const float* __restrict__ B,
              float* __restrict__ D, int K, int lda, int ldb, int ldc,
              long long sA, long long sB, long long sD,
              const float* __restrict__ bias, float alpha,
              const float* __restrict__ resid) {
    extern __shared__ float smem[];
    const int tid = threadIdx.x;
    const int lane = tid & 31;
    const int warp = tid >> 5;
    const int gid = lane >> 2;   // 0..7
    const int tig = lane & 3;    // 0..3
    const int wm = warp & 1;     // m half (64 rows)
    const int wn = warp >> 1;    // n quarter (32 cols)
    const int m0 = blockIdx.y * 128;
    const int n0 = blockIdx.x * 128;
    const int bz = blockIdx.z;

    A += (long long)bz * sA;
    B += (long long)bz * sB;
    D += (long long)bz * sD;
    if (EPI == 4) resid += (long long)bz * sD;

    // tile load geometry: row lm + u*32 (u=0..3), 4 consecutive k at lk
    const int lm = tid >> 3;          // 0..31
    const int lk = (tid & 7) * 4;     // 0,4,...,28
    const float* Ap = A + (long long)(m0 + lm) * lda + lk;
    const float* Bp = B + (long long)(n0 + lm) * ldb + lk;

    float acc[4][4][4];
#pragma unroll
    for (int i = 0; i < 4; i++)
#pragma unroll
        for (int j = 0; j < 4; j++)
#pragma unroll
            for (int r = 0; r < 4; r++) acc[i][j][r] = 0.f;

    const int nch = K / 32;
    float4 ra[4], rb[4];
#pragma unroll
    for (int u = 0; u < 4; u++) {
        ra[u] = *reinterpret_cast<const float4*>(Ap + (long long)u * 32 * lda);
        rb[u] = *reinterpret_cast<const float4*>(Bp + (long long)u * 32 * ldb);
    }

    for (int i = 0; i < nch; i++) {
        float* As = smem + (i & 1) * BUF_FLOATS;
        float* Bs = As + TILE_FLOATS;
        // store (converted to tf32)
#pragma unroll
        for (int u = 0; u < 4; u++) {
            float4 t = ra[u];
            t.x = to_tf32(t.x); t.y = to_tf32(t.y);
            t.z = to_tf32(t.z); t.w = to_tf32(t.w);
            *reinterpret_cast<float4*>(&As[(lm + u * 32) * PITCH + lk]) = t;
            float4 v = rb[u];
            v.x = to_tf32(v.x); v.y = to_tf32(v.y);
            v.z = to_tf32(v.z); v.w = to_tf32(v.w);
            *reinterpret_cast<float4*>(&Bs[(lm + u * 32) * PITCH + lk]) = v;
        }
        __syncthreads();
        if (i + 1 < nch) {
            const float* Ap2 = Ap + (i + 1) * 32;
            const float* Bp2 = Bp + (i + 1) * 32;
#pragma unroll
            for (int u = 0; u < 4; u++) {
                ra[u] = *reinterpret_cast<const float4*>(Ap2 + (long long)u * 32 * lda);
                rb[u] = *reinterpret_cast<const float4*>(Bp2 + (long long)u * 32 * ldb);
            }
        }
        // 4 k-steps of 8
#pragma unroll
        for (int ks = 0; ks < 4; ks++) {
            const int kk = ks * 8;
            uint32_t afr[4][4], bfr[4][2];
#pragma unroll
            for (int mt = 0; mt < 4; mt++) {
                const int mr = (wm * 64 + mt * 16 + gid) * PITCH;
                afr[mt][0] = __float_as_uint(As[mr + kk + tig]);
                afr[mt][1] = __float_as_uint(As[mr + 8 * PITCH + kk + tig]);
                afr[mt][2] = __float_as_uint(As[mr + kk + tig + 4]);
                afr[mt][3] = __float_as_uint(As[mr + 8 * PITCH + kk + tig + 4]);
            }
#pragma unroll
            for (int nt = 0; nt < 4; nt++) {
                const int nr = (wn * 32 + nt * 8 + gid) * PITCH;
                bfr[nt][0] = __float_as_uint(Bs[nr + kk + tig]);
                bfr[nt][1] = __float_as_uint(Bs[nr + kk + tig + 4]);
            }
#pragma unroll
            for (int mt = 0; mt < 4; mt++)
#pragma unroll
                for (int nt = 0; nt < 4; nt++)
                    mma_tf32(acc[mt][nt], afr[mt], bfr[nt]);
        }
        // next STS targets the other buffer; the per-iteration sync above
        // guarantees all reads of that buffer (from i-1) completed.
    }

    // epilogue
#pragma unroll
    for (int mt = 0; mt < 4; mt++) {
        const int m = m0 + wm * 64 + mt * 16 + gid;
#pragma unroll
        for (int nt = 0; nt < 4; nt++) {
            const int n = n0 + wn * 32 + nt * 8 + tig * 2;
            float* c = acc[mt][nt];
            if (EPI == 2) {
                const float b0v = bias[n], b1v = bias[n + 1];
                D[(long long)n * ldc + m]           = c[0] + b0v;
                D[(long long)(n + 1) * ldc + m]     = c[1] + b1v;
                D[(long long)n * ldc + m + 8]       = c[2] + b0v;
                D[(long long)(n + 1) * ldc + m + 8] = c[3] + b1v;
            } else {
                float2 lo = make_float2(c[0], c[1]);
                float2 hi = make_float2(c[2], c[3]);
                if (EPI == 1) {
                    const float b0v = bias[n], b1v = bias[n + 1];
                    lo.x += b0v; lo.y += b1v; hi.x += b0v; hi.y += b1v;
                } else if (EPI == 3) {
                    lo.x *= alpha; lo.y *= alpha; hi.x *= alpha; hi.y *= alpha;
                } else if (EPI == 4) {
                    const float bm0 = bias[m], bm1 = bias[m + 8];
                    const float2 r0 = *reinterpret_cast<const float2*>(
                        &resid[(long long)m * ldc + n]);
                    const float2 r1 = *reinterpret_cast<const float2*>(
                        &resid[(long long)(m + 8) * ldc + n]);
                    lo.x += bm0 + r0.x; lo.y += bm0 + r0.y;
                    hi.x += bm1 + r1.x; hi.y += bm1 + r1.y;
                }
                *reinterpret_cast<float2*>(&D[(long long)m * ldc + n]) = lo;
                *reinterpret_cast<float2*>(&D[(long long)(m + 8) * ldc + n]) = hi;
            }
        }
    }
}

// ============================================================================
// Row softmax over L=2048 (one 256-thread block per row)
// ============================================================================
__global__ __launch_bounds__(256)
void softmax_kernel(float* __restrict__ S) {
    float4* row = reinterpret_cast<float4*>(S + (size_t)blockIdx.x * LDIM);
    const int t = threadIdx.x;
    float4 v0 = row[t];
    float4 v1 = row[t + 256];

    float m = fmaxf(fmaxf(fmaxf(v0.x, v0.y), fmaxf(v0.z, v0.w)),
                    fmaxf(fmaxf(v1.x, v1.y), fmaxf(v1.z, v1.w)));
    __shared__ float sh[8];
    int lane = t & 31, wid = t >> 5;
    m = warp_max(m);
    if (lane == 0) sh[wid] = m;
    __syncthreads();
    if (wid == 0) {
        float mm = (lane < 8) ? sh[lane] : -3.4e38f;
        mm = warp_max(mm);
        if (lane == 0) sh[0] = mm;
    }
    __syncthreads();
    m = sh[0];
    __syncthreads();

    v0.x = __expf(v0.x - m); v0.y = __expf(v0.y - m);
    v0.z = __expf(v0.z - m); v0.w = __expf(v0.w - m);
    v1.x = __expf(v1.x - m); v1.y = __expf(v1.y - m);
    v1.z = __expf(v1.z - m); v1.w = __expf(v1.w - m);

    float s = v0.x + v0.y + v0.z + v0.w + v1.x + v1.y + v1.z + v1.w;
    s = warp_sum(s);
    if (lane == 0) sh[wid] = s;
    __syncthreads();
    if (wid == 0) {
        float t2 = (lane < 8) ? sh[lane] : 0.f;
        t2 = warp_sum(t2);
        if (lane == 0) sh[0] = t2;
    }
    __syncthreads();
    const float inv = 1.f / sh[0];

    v0.x *= inv; v0.y *= inv; v0.z *= inv; v0.w *= inv;
    v1.x *= inv; v1.y *= inv; v1.z *= inv; v1.w *= inv;
    row[t] = v0;
    row[t + 256] = v1;
}

// ============================================================================
// Launch
// ============================================================================
extern "C" void kernel_launch(void* const* d_in, const int* in_sizes, int n_in,
                              void* d_out, int out_size) {
    (void)in_sizes; (void)n_in; (void)out_size;
    const float* x   = (const float*)d_in[0];
    const float* gns = (const float*)d_in[1];
    const float* gnb = (const float*)d_in[2];
    const float* wq  = (const float*)d_in[3];
    const float* bq  = (const float*)d_in[4];
    const float* wk  = (const float*)d_in[5];
    const float* bk  = (const float*)d_in[6];
    const float* wv  = (const float*)d_in[7];
    const float* bv  = (const float*)d_in[8];
    const float* wo  = (const float*)d_in[9];
    const float* bo  = (const float*)d_in[10];
    float* out = (float*)d_out;

    float* scratch = nullptr;
    cudaGetSymbolAddress((void**)&scratch, g_scratch);
    float* ht = scratch;
    float* q  = scratch + 1 * SZ;
    float* k  = scratch + 2 * SZ;
    float* vT = scratch + 3 * SZ;
    float* a  = scratch + 4 * SZ;
    float* s  = scratch + 5 * SZ;

    const float attn_scale = 0.044194173824159216f;  // 512^-0.5

    static bool attr_done = false;
    if (!attr_done) {
        cudaFuncSetAttribute(gemm_mma<0>, cudaFuncAttributeMaxDynamicSharedMemorySize, GEMM_SMEM);
        cudaFuncSetAttribute(gemm_mma<1>, cudaFuncAttributeMaxDynamicSharedMemorySize, GEMM_SMEM);
        cudaFuncSetAttribute(gemm_mma<2>, cudaFuncAttributeMaxDynamicSharedMemorySize, GEMM_SMEM);
        cudaFuncSetAttribute(gemm_mma<3>, cudaFuncAttributeMaxDynamicSharedMemorySize, GEMM_SMEM);
        cudaFuncSetAttribute(gemm_mma<4>, cudaFuncAttributeMaxDynamicSharedMemorySize, GEMM_SMEM);
        attr_done = true;
    }

    // 1) GroupNorm + transpose: ht [B, L, C]
    gn_t_kernel<<<BDIM * NGRP, 256>>>(x, gns, gnb, ht);

    // 2) QKV projections (M=L, N=C, K=C); V written transposed as vT [C, L]
    {
        dim3 grid(CDIM / 128, LDIM / 128, BDIM);
        gemm_mma<1><<<grid, 256, GEMM_SMEM>>>(ht, wq, q, CDIM, CDIM, CDIM, CDIM,
            STRIDE_CL, 0, STRIDE_CL, bq, 0.f, nullptr);
        gemm_mma<1><<<grid, 256, GEMM_SMEM>>>(ht, wk, k, CDIM, CDIM, CDIM, CDIM,
            STRIDE_CL, 0, STRIDE_CL, bk, 0.f, nullptr);
        gemm_mma<2><<<grid, 256, GEMM_SMEM>>>(ht, wv, vT, CDIM, CDIM, CDIM, LDIM,
            STRIDE_CL, 0, STRIDE_CL, bv, 0.f, nullptr);
    }

    // 3) Scores: s[i,j] = scale * q[i,:].k[j,:]   (M=N=L, K=C)
    {
        dim3 grid(LDIM / 128, LDIM / 128, BDIM);
        gemm_mma<3><<<grid, 256, GEMM_SMEM>>>(q, k, s, CDIM, CDIM, CDIM, LDIM,
            STRIDE_CL, STRIDE_CL, STRIDE_LL, nullptr, attn_scale, nullptr);
    }

    // 4) Softmax rows
    softmax_kernel<<<BDIM * LDIM, 256>>>(s);

    // 5) a[i,c] = sum_j p[i,j] * vT[c,j]   (M=L, N=C, K=L)
    {
        dim3 grid(CDIM / 128, LDIM / 128, BDIM);
        gemm_mma<0><<<grid, 256, GEMM_SMEM>>>(s, vT, a, LDIM, LDIM, LDIM, CDIM,
            STRIDE_LL, STRIDE_CL, STRIDE_CL, nullptr, 0.f, nullptr);
    }

    // 6) out[o,l] = sum_c wo[o,c] * a[l,c] + bo[o] + x[o,l]  (M=C, N=L, K=C)
    {
        dim3 grid(LDIM / 128, CDIM / 128, BDIM);
        gemm_mma<4><<<grid, 256, GEMM_SMEM>>>(wo, a, out, CDIM, CDIM, CDIM, LDIM,
            0, STRIDE_CL, STRIDE_CL, bo, 0.f, x);
    }
}

// round 5
// speedup vs baseline: 3.9310x; 1.5891x over previous
#include <cuda_runtime.h>
#include <cuda_bf16.h>
#include <cstdint>

// Problem: x [B=8, C=512, L=2048], GroupNorm(32) -> QKV -> attention -> O-proj + residual.
#define BDIM 8
#define CDIM 512
#define LDIM 2048
#define NGRP 32
#define CPG  (CDIM / NGRP)   // 16
#define GN_EPS 1e-5f

#define STRIDE_CL ((long long)CDIM * LDIM)
#define STRIDE_LL ((long long)LDIM * LDIM)

// Scratch: ht [B,L,C] | q [B,L,C] | k [B,L,C] | vT [B,C,L] | a [B,L,C] | s [B,L,L]
#define SZ   ((size_t)BDIM * CDIM * LDIM)
#define SSZ  ((size_t)BDIM * LDIM * LDIM)
__device__ __align__(256) float g_scratch[5 * SZ + SSZ];

// ---------------------------------------------------------------------------
__device__ __forceinline__ float warp_sum(float v) {
#pragma unroll
    for (int o = 16; o > 0; o >>= 1) v += __shfl_xor_sync(0xFFFFFFFFu, v, o);
    return v;
}
__device__ __forceinline__ float warp_max(float v) {
#pragma unroll
    for (int o = 16; o > 0; o >>= 1) v = fmaxf(v, __shfl_xor_sync(0xFFFFFFFFu, v, o));
    return v;
}
// portable tensor-core MMA (sm_80+): D[16x8] += A[16x8] * B[8x8] (tf32)
__device__ __forceinline__ void mma_tf32(float* c, const uint32_t* a, const uint32_t* b) {
    asm volatile(
        "mma.sync.aligned.m16n8k8.row.col.f32.tf32.tf32.f32 "
        "{%0,%1,%2,%3}, {%4,%5,%6,%7}, {%8,%9}, {%0,%1,%2,%3};"
        : "+f"(c[0]), "+f"(c[1]), "+f"(c[2]), "+f"(c[3])
        : "r"(a[0]), "r"(a[1]), "r"(a[2]), "r"(a[3]), "r"(b[0]), "r"(b[1]));
}
__device__ __forceinline__ void cp_async16(uint32_t dst, const void* src) {
    asm volatile("cp.async.cg.shared.global [%0], [%1], 16;" :: "r"(dst), "l"(src));
}
__device__ __forceinline__ void cp_commit() {
    asm volatile("cp.async.commit_group;" ::: "memory");
}
template<int N>
__device__ __forceinline__ void cp_wait() {
    asm volatile("cp.async.wait_group %0;" :: "n"(N) : "memory");
}

// ============================================================================
// GroupNorm fused with transpose: x [B,C,L] -> ht [B,L,C]
// ============================================================================
__global__ __launch_bounds__(256)
void gn_t_kernel(const float* __restrict__ x, const float* __restrict__ gamma,
                 const float* __restrict__ beta, float* __restrict__ ht) {
    const int b = blockIdx.x / NGRP;
    const int g = blockIdx.x % NGRP;
    const size_t base = ((size_t)b * CDIM + (size_t)g * CPG) * LDIM;
    const float4* xp = reinterpret_cast<const float4*>(x + base);

    const int n4 = CPG * LDIM / 4;  // 8192
    float s = 0.f, ss = 0.f;
    for (int i = threadIdx.x; i < n4; i += 256) {
        float4 t = xp[i];
        s  += t.x + t.y + t.z + t.w;
        ss += t.x * t.x + t.y * t.y + t.z * t.z + t.w * t.w;
    }
    __shared__ float sh1[8], sh2[8];
    __shared__ float scg[CPG], sbg[CPG];
    int lane = threadIdx.x & 31, wid = threadIdx.x >> 5;
    s = warp_sum(s); ss = warp_sum(ss);
    if (lane == 0) { sh1[wid] = s; sh2[wid] = ss; }
    __syncthreads();
    if (wid == 0) {
        s  = (lane < 8) ? sh1[lane] : 0.f;
        ss = (lane < 8) ? sh2[lane] : 0.f;
        s = warp_sum(s); ss = warp_sum(ss);
        if (lane == 0) { sh1[0] = s; sh2[0] = ss; }
    }
    __syncthreads();
    const float inv_n = 1.f / (float)(CPG * LDIM);
    const float mean = sh1[0] * inv_n;
    const float var  = sh2[0] * inv_n - mean * mean;
    const float rstd = rsqrtf(var + GN_EPS);
    if (threadIdx.x < CPG) {
        float sc = gamma[g * CPG + threadIdx.x] * rstd;
        scg[threadIdx.x] = sc;
        sbg[threadIdx.x] = beta[g * CPG + threadIdx.x] - mean * sc;
    }
    __syncthreads();

    __shared__ float tile[CPG][133];
    for (int l0 = 0; l0 < LDIM; l0 += 128) {
        for (int it = threadIdx.x; it < 512; it += 256) {
            int c  = it >> 5;
            int l4 = (it & 31) * 4;
            float4 t = *reinterpret_cast<const float4*>(&x[base + (size_t)c * LDIM + l0 + l4]);
            float sc = scg[c], sb = sbg[c];
            tile[c][l4 + 0] = t.x * sc + sb;
            tile[c][l4 + 1] = t.y * sc + sb;
            tile[c][l4 + 2] = t.z * sc + sb;
            tile[c][l4 + 3] = t.w * sc + sb;
        }
        __syncthreads();
        for (int it = threadIdx.x; it < 512; it += 256) {
            int l  = it >> 2;
            int c4 = (it & 3) * 4;
            float4 o;
            o.x = tile[c4 + 0][l]; o.y = tile[c4 + 1][l];
            o.z = tile[c4 + 2][l]; o.w = tile[c4 + 3][l];
            *reinterpret_cast<float4*>(
                &ht[((size_t)b * LDIM + l0 + l) * CDIM + g * CPG + c4]) = o;
        }
        __syncthreads();
    }
}

// ============================================================================
// Tensor-core tf32 GEMM: D[m,n] = sum_k A[m,k]*B[n,k]  (A:[M,K], B:[N,K])
// CTA: 256 thr, 128x128 tile. Warp grid 2(m) x 4(n); warp tile 64x32.
// K-chunk 32, 3-stage cp.async pipeline, XOR-swizzled 128B smem rows.
// EPI: 0=none 1=+bias[n] 2=transposed D[n*ldc+m]+bias[n] 3=*alpha
//      4=+bias[m]+resid[m*ldc+n]
// smem stage: A 128x32 fl (16KB) + B 128x32 fl (16KB) = 32KB; 3 stages = 96KB.
// ============================================================================
#define STAGE_FLOATS 8192
#define STAGE_BYTES  32768
#define GEMM_SMEM    (3 * STAGE_BYTES)

// swizzled float index for element (row, kf) in a 128x32 tile
__device__ __forceinline__ int swz(int row, int kf) {
    return row * 32 + ((((kf >> 2) ^ row) & 7) << 2) + (kf & 3);
}

template<int EPI>
__global__ __launch_bounds__(256, 2)
void gemm_mma(const float* __restrict__ A, const float* __restrict__ B,
              float* __restrict__ D, int K, int lda, int ldb, int ldc,
              long long sA, long long sB, long long sD,
              const float* __restrict__ bias, float alpha,
              const float* __restrict__ resid) {
    extern __shared__ float smem[];
    const uint32_t sb = (uint32_t)__cvta_generic_to_shared(smem);
    const int tid = threadIdx.x;
    const int lane = tid & 31;
    const int warp = tid >> 5;
    const int gid = lane >> 2;   // 0..7
    const int tig = lane & 3;    // 0..3
    const int wm = warp & 1;     // m half (64 rows)
    const int wn = warp >> 1;    // n quarter (32 cols)
    const int m0 = blockIdx.y * 128;
    const int n0 = blockIdx.x * 128;
    const int bz = blockIdx.z;

    A += (long long)bz * sA;
    B += (long long)bz * sB;
    D += (long long)bz * sD;
    if (EPI == 4) resid += (long long)bz * sD;

    // load geometry: rows lm + u*32 (u=0..3), float4 at k-offset lk
    const int lm = tid >> 3;          // 0..31
    const int lk = (tid & 7) * 4;     // 0,4,...,28
    const float* Ap = A + (long long)(m0 + lm) * lda + lk;
    const float* Bp = B + (long long)(n0 + lm) * ldb + lk;
    // swizzle group is invariant across u (row step 32 keeps row&7 fixed)
    const uint32_t sts_off = (uint32_t)(lm * 128 + ((((lk >> 2) ^ lm) & 7) << 4));

    const int nch = K / 32;

#define ISSUE_STAGE(s, buf) do {                                              \
        const uint32_t d0 = sb + (uint32_t)(buf) * STAGE_BYTES + sts_off;     \
        const float* ap = Ap + (s) * 32;                                      \
        const float* bp = Bp + (s) * 32;                                      \
        _Pragma("unroll")                                                     \
        for (int u = 0; u < 4; u++)                                           \
            cp_async16(d0 + u * 4096, ap + (long long)u * 32 * lda);          \
        _Pragma("unroll")                                                     \
        for (int u = 0; u < 4; u++)                                           \
            cp_async16(d0 + 16384 + u * 4096, bp + (long long)u * 32 * ldb);  \
    } while (0)

    ISSUE_STAGE(0, 0); cp_commit();
    ISSUE_STAGE(1, 1); cp_commit();

    float acc[4][4][4];
#pragma unroll
    for (int i = 0; i < 4; i++)
#pragma unroll
        for (int j = 0; j < 4; j++)
#pragma unroll
            for (int r = 0; r < 4; r++) acc[i][j][r] = 0.f;

    for (int i = 0; i < nch; i++) {
        cp_wait<1>();
        __syncthreads();
        if (i + 2 < nch) ISSUE_STAGE(i + 2, (i + 2) % 3);
        cp_commit();

        const float* As = smem + (i % 3) * STAGE_FLOATS;
        const float* Bs = As + 4096;
#pragma unroll
        for (int ks = 0; ks < 4; ks++) {
            const int kk = ks * 8;
            uint32_t afr[4][4], bfr[4][2];
#pragma unroll
            for (int mt = 0; mt < 4; mt++) {
                const int r = wm * 64 + mt * 16 + gid;
                afr[mt][0] = __float_as_uint(As[swz(r,     kk + tig)]);
                afr[mt][1] = __float_as_uint(As[swz(r + 8, kk + tig)]);
                afr[mt][2] = __float_as_uint(As[swz(r,     kk + tig + 4)]);
                afr[mt][3] = __float_as_uint(As[swz(r + 8, kk + tig + 4)]);
            }
#pragma unroll
            for (int nt = 0; nt < 4; nt++) {
                const int r = wn * 32 + nt * 8 + gid;
                bfr[nt][0] = __float_as_uint(Bs[swz(r, kk + tig)]);
                bfr[nt][1] = __float_as_uint(Bs[swz(r, kk + tig + 4)]);
            }
#pragma unroll
            for (int mt = 0; mt < 4; mt++)
#pragma unroll
                for (int nt = 0; nt < 4; nt++)
                    mma_tf32(acc[mt][nt], afr[mt], bfr[nt]);
        }
    }
#undef ISSUE_STAGE

    // epilogue
#pragma unroll
    for (int mt = 0; mt < 4; mt++) {
        const int m = m0 + wm * 64 + mt * 16 + gid;
#pragma unroll
        for (int nt = 0; nt < 4; nt++) {
            const int n = n0 + wn * 32 + nt * 8 + tig * 2;
            float* c = acc[mt][nt];
            if (EPI == 2) {
                const float b0v = bias[n], b1v = bias[n + 1];
                D[(long long)n * ldc + m]           = c[0] + b0v;
                D[(long long)(n + 1) * ldc + m]     = c[1] + b1v;
                D[(long long)n * ldc + m + 8]       = c[2] + b0v;
                D[(long long)(n + 1) * ldc + m + 8] = c[3] + b1v;
            } else {
                float2 lo = make_float2(c[0], c[1]);
                float2 hi = make_float2(c[2], c[3]);
                if (EPI == 1) {
                    const float b0v = bias[n], b1v = bias[n + 1];
                    lo.x += b0v; lo.y += b1v; hi.x += b0v; hi.y += b1v;
                } else if (EPI == 3) {
                    lo.x *= alpha; lo.y *= alpha; hi.x *= alpha; hi.y *= alpha;
                } else if (EPI == 4) {
                    const float bm0 = bias[m], bm1 = bias[m + 8];
                    const float2 r0 = *reinterpret_cast<const float2*>(
                        &resid[(long long)m * ldc + n]);
                    const float2 r1 = *reinterpret_cast<const float2*>(
                        &resid[(long long)(m + 8) * ldc + n]);
                    lo.x += bm0 + r0.x; lo.y += bm0 + r0.y;
                    hi.x += bm1 + r1.x; hi.y += bm1 + r1.y;
                }
                *reinterpret_cast<float2*>(&D[(long long)m * ldc + n]) = lo;
                *reinterpret_cast<float2*>(&D[(long long)(m + 8) * ldc + n]) = hi;
            }
        }
    }
}

// ============================================================================
// Row softmax over L=2048 (one 256-thread block per row)
// ============================================================================
__global__ __launch_bounds__(256)
void softmax_kernel(float* __restrict__ S) {
    float4* row = reinterpret_cast<float4*>(S + (size_t)blockIdx.x * LDIM);
    const int t = threadIdx.x;
    float4 v0 = row[t];
    float4 v1 = row[t + 256];

    float m = fmaxf(fmaxf(fmaxf(v0.x, v0.y), fmaxf(v0.z, v0.w)),
                    fmaxf(fmaxf(v1.x, v1.y), fmaxf(v1.z, v1.w)));
    __shared__ float sh[8];
    int lane = t & 31, wid = t >> 5;
    m = warp_max(m);
    if (lane == 0) sh[wid] = m;
    __syncthreads();
    if (wid == 0) {
        float mm = (lane < 8) ? sh[lane] : -3.4e38f;
        mm = warp_max(mm);
        if (lane == 0) sh[0] = mm;
    }
    __syncthreads();
    m = sh[0];
    __syncthreads();

    v0.x = __expf(v0.x - m); v0.y = __expf(v0.y - m);
    v0.z = __expf(v0.z - m); v0.w = __expf(v0.w - m);
    v1.x = __expf(v1.x - m); v1.y = __expf(v1.y - m);
    v1.z = __expf(v1.z - m); v1.w = __expf(v1.w - m);

    float s = v0.x + v0.y + v0.z + v0.w + v1.x + v1.y + v1.z + v1.w;
    s = warp_sum(s);
    if (lane == 0) sh[wid] = s;
    __syncthreads();
    if (wid == 0) {
        float t2 = (lane < 8) ? sh[lane] : 0.f;
        t2 = warp_sum(t2);
        if (lane == 0) sh[0] = t2;
    }
    __syncthreads();
    const float inv = 1.f / sh[0];

    v0.x *= inv; v0.y *= inv; v0.z *= inv; v0.w *= inv;
    v1.x *= inv; v1.y *= inv; v1.z *= inv; v1.w *= inv;
    row[t] = v0;
    row[t + 256] = v1;
}

// ============================================================================
// Launch
// ============================================================================
extern "C" void kernel_launch(void* const* d_in, const int* in_sizes, int n_in,
                              void* d_out, int out_size) {
    (void)in_sizes; (void)n_in; (void)out_size;
    const float* x   = (const float*)d_in[0];
    const float* gns = (const float*)d_in[1];
    const float* gnb = (const float*)d_in[2];
    const float* wq  = (const float*)d_in[3];
    const float* bq  = (const float*)d_in[4];
    const float* wk  = (const float*)d_in[5];
    const float* bk  = (const float*)d_in[6];
    const float* wv  = (const float*)d_in[7];
    const float* bv  = (const float*)d_in[8];
    const float* wo  = (const float*)d_in[9];
    const float* bo  = (const float*)d_in[10];
    float* out = (float*)d_out;

    float* scratch = nullptr;
    cudaGetSymbolAddress((void**)&scratch, g_scratch);
    float* ht = scratch;
    float* q  = scratch + 1 * SZ;
    float* k  = scratch + 2 * SZ;
    float* vT = scratch + 3 * SZ;
    float* a  = scratch + 4 * SZ;
    float* s  = scratch + 5 * SZ;

    const float attn_scale = 0.044194173824159216f;  // 512^-0.5

    static bool attr_done = false;
    if (!attr_done) {
        cudaFuncSetAttribute(gemm_mma<0>, cudaFuncAttributeMaxDynamicSharedMemorySize, GEMM_SMEM);
        cudaFuncSetAttribute(gemm_mma<1>, cudaFuncAttributeMaxDynamicSharedMemorySize, GEMM_SMEM);
        cudaFuncSetAttribute(gemm_mma<2>, cudaFuncAttributeMaxDynamicSharedMemorySize, GEMM_SMEM);
        cudaFuncSetAttribute(gemm_mma<3>, cudaFuncAttributeMaxDynamicSharedMemorySize, GEMM_SMEM);
        cudaFuncSetAttribute(gemm_mma<4>, cudaFuncAttributeMaxDynamicSharedMemorySize, GEMM_SMEM);
        attr_done = true;
    }

    // 1) GroupNorm + transpose: ht [B, L, C]
    gn_t_kernel<<<BDIM * NGRP, 256>>>(x, gns, gnb, ht);

    // 2) QKV projections (M=L, N=C, K=C); V written transposed as vT [C, L]
    {
        dim3 grid(CDIM / 128, LDIM / 128, BDIM);
        gemm_mma<1><<<grid, 256, GEMM_SMEM>>>(ht, wq, q, CDIM, CDIM, CDIM, CDIM,
            STRIDE_CL, 0, STRIDE_CL, bq, 0.f, nullptr);
        gemm_mma<1><<<grid, 256, GEMM_SMEM>>>(ht, wk, k, CDIM, CDIM, CDIM, CDIM,
            STRIDE_CL, 0, STRIDE_CL, bk, 0.f, nullptr);
        gemm_mma<2><<<grid, 256, GEMM_SMEM>>>(ht, wv, vT, CDIM, CDIM, CDIM, LDIM,
            STRIDE_CL, 0, STRIDE_CL, bv, 0.f, nullptr);
    }

    // 3) Scores: s[i,j] = scale * q[i,:].k[j,:]   (M=N=L, K=C)
    {
        dim3 grid(LDIM / 128, LDIM / 128, BDIM);
        gemm_mma<3><<<grid, 256, GEMM_SMEM>>>(q, k, s, CDIM, CDIM, CDIM, LDIM,
            STRIDE_CL, STRIDE_CL, STRIDE_LL, nullptr, attn_scale, nullptr);
    }

    // 4) Softmax rows
    softmax_kernel<<<BDIM * LDIM, 256>>>(s);

    // 5) a[i,c] = sum_j p[i,j] * vT[c,j]   (M=L, N=C, K=L)
    {
        dim3 grid(CDIM / 128, LDIM / 128, BDIM);
        gemm_mma<0><<<grid, 256, GEMM_SMEM>>>(s, vT, a, LDIM, LDIM, LDIM, CDIM,
            STRIDE_LL, STRIDE_CL, STRIDE_CL, nullptr, 0.f, nullptr);
    }

    // 6) out[o,l] = sum_c wo[o,c] * a[l,c] + bo[o] + x[o,l]  (M=C, N=L, K=C)
    {
        dim3 grid(LDIM / 128, CDIM / 128, BDIM);
        gemm_mma<4><<<grid, 256, GEMM_SMEM>>>(wo, a, out, CDIM, CDIM, CDIM, LDIM,
            0, STRIDE_CL, STRIDE_CL, bo, 0.f, x);
    }
}

// round 6
// speedup vs baseline: 4.3104x; 1.0965x over previous
#include <cuda_runtime.h>
#include <cuda_bf16.h>
#include <cstdint>

// Problem: x [B=8, C=512, L=2048], GroupNorm(32) -> QKV -> attention -> O-proj + residual.
#define BDIM 8
#define CDIM 512
#define LDIM 2048
#define NGRP 32
#define CPG  (CDIM / NGRP)   // 16
#define GN_EPS 1e-5f

#define STRIDE_CL ((long long)CDIM * LDIM)
#define STRIDE_LL ((long long)LDIM * LDIM)

// Scratch: ht [B,L,C] | q [B,L,C] | k [B,L,C] | vT [B,C,L] | a [B,L,C] | s [B,L,L]
#define SZ   ((size_t)BDIM * CDIM * LDIM)
#define SSZ  ((size_t)BDIM * LDIM * LDIM)
__device__ __align__(256) float g_scratch[5 * SZ + SSZ];

// ---------------------------------------------------------------------------
__device__ __forceinline__ float warp_sum(float v) {
#pragma unroll
    for (int o = 16; o > 0; o >>= 1) v += __shfl_xor_sync(0xFFFFFFFFu, v, o);
    return v;
}
__device__ __forceinline__ float warp_max(float v) {
#pragma unroll
    for (int o = 16; o > 0; o >>= 1) v = fmaxf(v, __shfl_xor_sync(0xFFFFFFFFu, v, o));
    return v;
}
// portable tensor-core MMA (sm_80+): D[16x8] += A[16x8] * B[8x8] (tf32)
__device__ __forceinline__ void mma_tf32(float* c, const uint32_t* a, const uint32_t* b) {
    asm volatile(
        "mma.sync.aligned.m16n8k8.row.col.f32.tf32.tf32.f32 "
        "{%0,%1,%2,%3}, {%4,%5,%6,%7}, {%8,%9}, {%0,%1,%2,%3};"
        : "+f"(c[0]), "+f"(c[1]), "+f"(c[2]), "+f"(c[3])
        : "r"(a[0]), "r"(a[1]), "r"(a[2]), "r"(a[3]), "r"(b[0]), "r"(b[1]));
}
__device__ __forceinline__ void cp_async16(uint32_t dst, const void* src) {
    asm volatile("cp.async.cg.shared.global [%0], [%1], 16;" :: "r"(dst), "l"(src));
}
__device__ __forceinline__ void cp_commit() {
    asm volatile("cp.async.commit_group;" ::: "memory");
}
template<int N>
__device__ __forceinline__ void cp_wait() {
    asm volatile("cp.async.wait_group %0;" :: "n"(N) : "memory");
}

// ============================================================================
// GroupNorm fused with transpose: x [B,C,L] -> ht [B,L,C]
// ============================================================================
__global__ __launch_bounds__(256)
void gn_t_kernel(const float* __restrict__ x, const float* __restrict__ gamma,
                 const float* __restrict__ beta, float* __restrict__ ht) {
    const int b = blockIdx.x / NGRP;
    const int g = blockIdx.x % NGRP;
    const size_t base = ((size_t)b * CDIM + (size_t)g * CPG) * LDIM;
    const float4* xp = reinterpret_cast<const float4*>(x + base);

    const int n4 = CPG * LDIM / 4;  // 8192
    float s = 0.f, ss = 0.f;
    for (int i = threadIdx.x; i < n4; i += 256) {
        float4 t = xp[i];
        s  += t.x + t.y + t.z + t.w;
        ss += t.x * t.x + t.y * t.y + t.z * t.z + t.w * t.w;
    }
    __shared__ float sh1[8], sh2[8];
    __shared__ float scg[CPG], sbg[CPG];
    int lane = threadIdx.x & 31, wid = threadIdx.x >> 5;
    s = warp_sum(s); ss = warp_sum(ss);
    if (lane == 0) { sh1[wid] = s; sh2[wid] = ss; }
    __syncthreads();
    if (wid == 0) {
        s  = (lane < 8) ? sh1[lane] : 0.f;
        ss = (lane < 8) ? sh2[lane] : 0.f;
        s = warp_sum(s); ss = warp_sum(ss);
        if (lane == 0) { sh1[0] = s; sh2[0] = ss; }
    }
    __syncthreads();
    const float inv_n = 1.f / (float)(CPG * LDIM);
    const float mean = sh1[0] * inv_n;
    const float var  = sh2[0] * inv_n - mean * mean;
    const float rstd = rsqrtf(var + GN_EPS);
    if (threadIdx.x < CPG) {
        float sc = gamma[g * CPG + threadIdx.x] * rstd;
        scg[threadIdx.x] = sc;
        sbg[threadIdx.x] = beta[g * CPG + threadIdx.x] - mean * sc;
    }
    __syncthreads();

    __shared__ float tile[CPG][133];
    for (int l0 = 0; l0 < LDIM; l0 += 128) {
        for (int it = threadIdx.x; it < 512; it += 256) {
            int c  = it >> 5;
            int l4 = (it & 31) * 4;
            float4 t = *reinterpret_cast<const float4*>(&x[base + (size_t)c * LDIM + l0 + l4]);
            float sc = scg[c], sb = sbg[c];
            tile[c][l4 + 0] = t.x * sc + sb;
            tile[c][l4 + 1] = t.y * sc + sb;
            tile[c][l4 + 2] = t.z * sc + sb;
            tile[c][l4 + 3] = t.w * sc + sb;
        }
        __syncthreads();
        for (int it = threadIdx.x; it < 512; it += 256) {
            int l  = it >> 2;
            int c4 = (it & 3) * 4;
            float4 o;
            o.x = tile[c4 + 0][l]; o.y = tile[c4 + 1][l];
            o.z = tile[c4 + 2][l]; o.w = tile[c4 + 3][l];
            *reinterpret_cast<float4*>(
                &ht[((size_t)b * LDIM + l0 + l) * CDIM + g * CPG + c4]) = o;
        }
        __syncthreads();
    }
}

// ============================================================================
// Tensor-core tf32 GEMM: D[m,n] = sum_k A[m,k]*B[n,k]  (A:[M,K], B:[N,K])
// CTA: 128 thr (4 warps), 128x128 tile. Warp grid 2(m) x 2(n); warp tile 64x64.
// K-chunk 32, 3-stage cp.async pipeline, XOR-swizzled 128B smem rows.
// EPI: 0=none 1=+bias[n] 2=transposed D[n*ldc+m]+bias[n] 3=*alpha
//      4=+bias[m]+resid[m*ldc+n]
// smem stage: A 128x32 fl (16KB) + B 128x32 fl (16KB) = 32KB; 3 stages = 96KB.
// ============================================================================
#define STAGE_FLOATS 8192
#define STAGE_BYTES  32768
#define GEMM_SMEM    (3 * STAGE_BYTES)

// swizzled float index for element (row, kf) in a 128x32 tile
__device__ __forceinline__ int swz(int row, int kf) {
    return row * 32 + ((((kf >> 2) ^ row) & 7) << 2) + (kf & 3);
}

template<int EPI>
__global__ __launch_bounds__(128, 2)
void gemm_mma(const float* __restrict__ A, const float* __restrict__ B,
              float* __restrict__ D, int K, int lda, int ldb, int ldc,
              long long sA, long long sB, long long sD,
              const float* __restrict__ bias, float alpha,
              const float* __restrict__ resid) {
    extern __shared__ float smem[];
    const uint32_t sb = (uint32_t)__cvta_generic_to_shared(smem);
    const int tid = threadIdx.x;
    const int lane = tid & 31;
    const int warp = tid >> 5;
    const int gid = lane >> 2;   // 0..7
    const int tig = lane & 3;    // 0..3
    const int wm = warp & 1;     // m half (64 rows)
    const int wn = warp >> 1;    // n half (64 cols)
    const int m0 = blockIdx.y * 128;
    const int n0 = blockIdx.x * 128;
    const int bz = blockIdx.z;

    A += (long long)bz * sA;
    B += (long long)bz * sB;
    D += (long long)bz * sD;
    if (EPI == 4) resid += (long long)bz * sD;

    // load geometry: rows lm + u*16 (u=0..7), float4 at k-offset lk
    const int lm = tid >> 3;          // 0..15
    const int lk = (tid & 7) * 4;     // 0,4,...,28
    const float* Ap = A + (long long)(m0 + lm) * lda + lk;
    const float* Bp = B + (long long)(n0 + lm) * ldb + lk;
    // swizzle group invariant across u (row step 16 keeps row&7 fixed)
    const uint32_t sts_off = (uint32_t)(lm * 128 + ((((lk >> 2) ^ lm) & 7) << 4));

    const int nch = K / 32;

#define ISSUE_STAGE(s, buf) do {                                              \
        const uint32_t d0 = sb + (uint32_t)(buf) * STAGE_BYTES + sts_off;     \
        const float* ap = Ap + (s) * 32;                                      \
        const float* bp = Bp + (s) * 32;                                      \
        _Pragma("unroll")                                                     \
        for (int u = 0; u < 8; u++)                                           \
            cp_async16(d0 + u * 2048, ap + (long long)u * 16 * lda);          \
        _Pragma("unroll")                                                     \
        for (int u = 0; u < 8; u++)                                           \
            cp_async16(d0 + 16384 + u * 2048, bp + (long long)u * 16 * ldb);  \
    } while (0)

    ISSUE_STAGE(0, 0); cp_commit();
    ISSUE_STAGE(1, 1); cp_commit();

    float acc[4][8][4];
#pragma unroll
    for (int i = 0; i < 4; i++)
#pragma unroll
        for (int j = 0; j < 8; j++)
#pragma unroll
            for (int r = 0; r < 4; r++) acc[i][j][r] = 0.f;

    for (int i = 0; i < nch; i++) {
        cp_wait<1>();
        __syncthreads();
        if (i + 2 < nch) ISSUE_STAGE(i + 2, (i + 2) % 3);
        cp_commit();

        const float* As = smem + (i % 3) * STAGE_FLOATS;
        const float* Bs = As + 4096;
#pragma unroll
        for (int ks = 0; ks < 4; ks++) {
            const int kk = ks * 8;
            uint32_t afr[4][4], bfr[8][2];
#pragma unroll
            for (int mt = 0; mt < 4; mt++) {
                const int r = wm * 64 + mt * 16 + gid;
                afr[mt][0] = __float_as_uint(As[swz(r,     kk + tig)]);
                afr[mt][1] = __float_as_uint(As[swz(r + 8, kk + tig)]);
                afr[mt][2] = __float_as_uint(As[swz(r,     kk + tig + 4)]);
                afr[mt][3] = __float_as_uint(As[swz(r + 8, kk + tig + 4)]);
            }
#pragma unroll
            for (int nt = 0; nt < 8; nt++) {
                const int r = wn * 64 + nt * 8 + gid;
                bfr[nt][0] = __float_as_uint(Bs[swz(r, kk + tig)]);
                bfr[nt][1] = __float_as_uint(Bs[swz(r, kk + tig + 4)]);
            }
#pragma unroll
            for (int mt = 0; mt < 4; mt++)
#pragma unroll
                for (int nt = 0; nt < 8; nt++)
                    mma_tf32(acc[mt][nt], afr[mt], bfr[nt]);
        }
    }
#undef ISSUE_STAGE

    // epilogue: warp covers rows wm*64 + mt*16 + {gid, gid+8}, cols wn*64 + nt*8 + tig*2
#pragma unroll
    for (int mt = 0; mt < 4; mt++) {
        const int m = m0 + wm * 64 + mt * 16 + gid;
#pragma unroll
        for (int nt = 0; nt < 8; nt++) {
            const int n = n0 + wn * 64 + nt * 8 + tig * 2;
            float* c = acc[mt][nt];
            if (EPI == 2) {
                const float b0v = bias[n], b1v = bias[n + 1];
                D[(long long)n * ldc + m]           = c[0] + b0v;
                D[(long long)(n + 1) * ldc + m]     = c[1] + b1v;
                D[(long long)n * ldc + m + 8]       = c[2] + b0v;
                D[(long long)(n + 1) * ldc + m + 8] = c[3] + b1v;
            } else {
                float2 lo = make_float2(c[0], c[1]);
                float2 hi = make_float2(c[2], c[3]);
                if (EPI == 1) {
                    const float b0v = bias[n], b1v = bias[n + 1];
                    lo.x += b0v; lo.y += b1v; hi.x += b0v; hi.y += b1v;
                } else if (EPI == 3) {
                    lo.x *= alpha; lo.y *= alpha; hi.x *= alpha; hi.y *= alpha;
                } else if (EPI == 4) {
                    const float bm0 = bias[m], bm1 = bias[m + 8];
                    const float2 r0 = *reinterpret_cast<const float2*>(
                        &resid[(long long)m * ldc + n]);
                    const float2 r1 = *reinterpret_cast<const float2*>(
                        &resid[(long long)(m + 8) * ldc + n]);
                    lo.x += bm0 + r0.x; lo.y += bm0 + r0.y;
                    hi.x += bm1 + r1.x; hi.y += bm1 + r1.y;
                }
                *reinterpret_cast<float2*>(&D[(long long)m * ldc + n]) = lo;
                *reinterpret_cast<float2*>(&D[(long long)(m + 8) * ldc + n]) = hi;
            }
        }
    }
}

// ============================================================================
// Row softmax over L=2048 (one 256-thread block per row)
// ============================================================================
__global__ __launch_bounds__(256)
void softmax_kernel(float* __restrict__ S) {
    float4* row = reinterpret_cast<float4*>(S + (size_t)blockIdx.x * LDIM);
    const int t = threadIdx.x;
    float4 v0 = row[t];
    float4 v1 = row[t + 256];

    float m = fmaxf(fmaxf(fmaxf(v0.x, v0.y), fmaxf(v0.z, v0.w)),
                    fmaxf(fmaxf(v1.x, v1.y), fmaxf(v1.z, v1.w)));
    __shared__ float sh[8];
    int lane = t & 31, wid = t >> 5;
    m = warp_max(m);
    if (lane == 0) sh[wid] = m;
    __syncthreads();
    if (wid == 0) {
        float mm = (lane < 8) ? sh[lane] : -3.4e38f;
        mm = warp_max(mm);
        if (lane == 0) sh[0] = mm;
    }
    __syncthreads();
    m = sh[0];
    __syncthreads();

    v0.x = __expf(v0.x - m); v0.y = __expf(v0.y - m);
    v0.z = __expf(v0.z - m); v0.w = __expf(v0.w - m);
    v1.x = __expf(v1.x - m); v1.y = __expf(v1.y - m);
    v1.z = __expf(v1.z - m); v1.w = __expf(v1.w - m);

    float s = v0.x + v0.y + v0.z + v0.w + v1.x + v1.y + v1.z + v1.w;
    s = warp_sum(s);
    if (lane == 0) sh[wid] = s;
    __syncthreads();
    if (wid == 0) {
        float t2 = (lane < 8) ? sh[lane] : 0.f;
        t2 = warp_sum(t2);
        if (lane == 0) sh[0] = t2;
    }
    __syncthreads();
    const float inv = 1.f / sh[0];

    v0.x *= inv; v0.y *= inv; v0.z *= inv; v0.w *= inv;
    v1.x *= inv; v1.y *= inv; v1.z *= inv; v1.w *= inv;
    row[t] = v0;
    row[t + 256] = v1;
}

// ============================================================================
// Launch
// ============================================================================
extern "C" void kernel_launch(void* const* d_in, const int* in_sizes, int n_in,
                              void* d_out, int out_size) {
    (void)in_sizes; (void)n_in; (void)out_size;
    const float* x   = (const float*)d_in[0];
    const float* gns = (const float*)d_in[1];
    const float* gnb = (const float*)d_in[2];
    const float* wq  = (const float*)d_in[3];
    const float* bq  = (const float*)d_in[4];
    const float* wk  = (const float*)d_in[5];
    const float* bk  = (const float*)d_in[6];
    const float* wv  = (const float*)d_in[7];
    const float* bv  = (const float*)d_in[8];
    const float* wo  = (const float*)d_in[9];
    const float* bo  = (const float*)d_in[10];
    float* out = (float*)d_out;

    float* scratch = nullptr;
    cudaGetSymbolAddress((void**)&scratch, g_scratch);
    float* ht = scratch;
    float* q  = scratch + 1 * SZ;
    float* k  = scratch + 2 * SZ;
    float* vT = scratch + 3 * SZ;
    float* a  = scratch + 4 * SZ;
    float* s  = scratch + 5 * SZ;

    const float attn_scale = 0.044194173824159216f;  // 512^-0.5

    static bool attr_done = false;
    if (!attr_done) {
        cudaFuncSetAttribute(gemm_mma<0>, cudaFuncAttributeMaxDynamicSharedMemorySize, GEMM_SMEM);
        cudaFuncSetAttribute(gemm_mma<1>, cudaFuncAttributeMaxDynamicSharedMemorySize, GEMM_SMEM);
        cudaFuncSetAttribute(gemm_mma<2>, cudaFuncAttributeMaxDynamicSharedMemorySize, GEMM_SMEM);
        cudaFuncSetAttribute(gemm_mma<3>, cudaFuncAttributeMaxDynamicSharedMemorySize, GEMM_SMEM);
        cudaFuncSetAttribute(gemm_mma<4>, cudaFuncAttributeMaxDynamicSharedMemorySize, GEMM_SMEM);
        attr_done = true;
    }

    // 1) GroupNorm + transpose: ht [B, L, C]
    gn_t_kernel<<<BDIM * NGRP, 256>>>(x, gns, gnb, ht);

    // 2) QKV projections (M=L, N=C, K=C); V written transposed as vT [C, L]
    {
        dim3 grid(CDIM / 128, LDIM / 128, BDIM);
        gemm_mma<1><<<grid, 128, GEMM_SMEM>>>(ht, wq, q, CDIM, CDIM, CDIM, CDIM,
            STRIDE_CL, 0, STRIDE_CL, bq, 0.f, nullptr);
        gemm_mma<1><<<grid, 128, GEMM_SMEM>>>(ht, wk, k, CDIM, CDIM, CDIM, CDIM,
            STRIDE_CL, 0, STRIDE_CL, bk, 0.f, nullptr);
        gemm_mma<2><<<grid, 128, GEMM_SMEM>>>(ht, wv, vT, CDIM, CDIM, CDIM, LDIM,
            STRIDE_CL, 0, STRIDE_CL, bv, 0.f, nullptr);
    }

    // 3) Scores: s[i,j] = scale * q[i,:].k[j,:]   (M=N=L, K=C)
    {
        dim3 grid(LDIM / 128, LDIM / 128, BDIM);
        gemm_mma<3><<<grid, 128, GEMM_SMEM>>>(q, k, s, CDIM, CDIM, CDIM, LDIM,
            STRIDE_CL, STRIDE_CL, STRIDE_LL, nullptr, attn_scale, nullptr);
    }

    // 4) Softmax rows
    softmax_kernel<<<BDIM * LDIM, 256>>>(s);

    // 5) a[i,c] = sum_j p[i,j] * vT[c,j]   (M=L, N=C, K=L)
    {
        dim3 grid(CDIM / 128, LDIM / 128, BDIM);
        gemm_mma<0><<<grid, 128, GEMM_SMEM>>>(s, vT, a, LDIM, LDIM, LDIM, CDIM,
            STRIDE_LL, STRIDE_CL, STRIDE_CL, nullptr, 0.f, nullptr);
    }

    // 6) out[o,l] = sum_c wo[o,c] * a[l,c] + bo[o] + x[o,l]  (M=C, N=L, K=C)
    {
        dim3 grid(LDIM / 128, CDIM / 128, BDIM);
        gemm_mma<4><<<grid, 128, GEMM_SMEM>>>(wo, a, out, CDIM, CDIM, CDIM, LDIM,
            0, STRIDE_CL, STRIDE_CL, bo, 0.f, x);
    }
}

// round 7
// speedup vs baseline: 7.3745x; 1.7109x over previous
#include <cuda_runtime.h>
#include <cuda_fp16.h>
#include <cstdint>

// Problem: x [B=8, C=512, L=2048], GroupNorm(32) -> QKV -> attention -> O-proj + residual.
#define BDIM 8
#define CDIM 512
#define LDIM 2048
#define NGRP 32
#define CPG  (CDIM / NGRP)   // 16
#define GN_EPS 1e-5f

#define CL 1048576LL   // C*L per-batch elems
#define LL 4194304LL   // L*L per-batch elems

// Scratch (bytes):
//  ht  [B,L,C] fp16 @ 0          (16,777,216)
//  qh  [B,L,C] fp16 @ 16777216
//  kh  [B,L,C] fp16 @ 33554432
//  vTh [B,C,L] fp16 @ 50331648
//  ah  [B,L,C] fp16 @ 67108864
//  s   [B,L,L] fp32 @ 83886080   (134,217,728)
//  p   [B,L,L] fp16 @ 218103808  (67,108,864)
//  wh  4x[C,C] fp16 @ 285212672  (2,097,152)
__device__ __align__(256) unsigned char g_scratch[287309824];

// ---------------------------------------------------------------------------
__device__ __forceinline__ float warp_sum(float v) {
#pragma unroll
    for (int o = 16; o > 0; o >>= 1) v += __shfl_xor_sync(0xFFFFFFFFu, v, o);
    return v;
}
__device__ __forceinline__ float warp_max(float v) {
#pragma unroll
    for (int o = 16; o > 0; o >>= 1) v = fmaxf(v, __shfl_xor_sync(0xFFFFFFFFu, v, o));
    return v;
}
// fp16 MMA, fp32 accumulate: D[16x8] += A[16x16] * B[16x8]
__device__ __forceinline__ void mma_f16(float* c, const uint32_t* a, const uint32_t* b) {
    asm volatile(
        "mma.sync.aligned.m16n8k16.row.col.f32.f16.f16.f32 "
        "{%0,%1,%2,%3}, {%4,%5,%6,%7}, {%8,%9}, {%0,%1,%2,%3};"
        : "+f"(c[0]), "+f"(c[1]), "+f"(c[2]), "+f"(c[3])
        : "r"(a[0]), "r"(a[1]), "r"(a[2]), "r"(a[3]), "r"(b[0]), "r"(b[1]));
}
__device__ __forceinline__ void cp_async16(uint32_t dst, const void* src) {
    asm volatile("cp.async.cg.shared.global [%0], [%1], 16;" :: "r"(dst), "l"(src));
}
__device__ __forceinline__ void cp_commit() {
    asm volatile("cp.async.commit_group;" ::: "memory");
}
template<int N>
__device__ __forceinline__ void cp_wait() {
    asm volatile("cp.async.wait_group %0;" :: "n"(N) : "memory");
}

// ============================================================================
// Weight convert: 4 x [C,C] fp32 -> fp16 (wq | wk | wv | wo)
// ============================================================================
__global__ __launch_bounds__(256)
void conv_w_kernel(const float* __restrict__ wq, const float* __restrict__ wk,
                   const float* __restrict__ wv, const float* __restrict__ wo,
                   __half* __restrict__ dst) {
    int i = blockIdx.x * 256 + threadIdx.x;        // 0 .. 4*262144-1
    int which = i >> 18;
    int off = i & 0x3FFFF;
    const float* src = (which == 0) ? wq : (which == 1) ? wk : (which == 2) ? wv : wo;
    dst[i] = __float2half(src[off]);
}

// ============================================================================
// GroupNorm fused with transpose: x [B,C,L] fp32 -> ht [B,L,C] fp16
// ============================================================================
__global__ __launch_bounds__(256)
void gn_t_kernel(const float* __restrict__ x, const float* __restrict__ gamma,
                 const float* __restrict__ beta, __half* __restrict__ ht) {
    const int b = blockIdx.x / NGRP;
    const int g = blockIdx.x % NGRP;
    const size_t base = ((size_t)b * CDIM + (size_t)g * CPG) * LDIM;
    const float4* xp = reinterpret_cast<const float4*>(x + base);

    const int n4 = CPG * LDIM / 4;  // 8192
    float s = 0.f, ss = 0.f;
    for (int i = threadIdx.x; i < n4; i += 256) {
        float4 t = xp[i];
        s  += t.x + t.y + t.z + t.w;
        ss += t.x * t.x + t.y * t.y + t.z * t.z + t.w * t.w;
    }
    __shared__ float sh1[8], sh2[8];
    __shared__ float scg[CPG], sbg[CPG];
    int lane = threadIdx.x & 31, wid = threadIdx.x >> 5;
    s = warp_sum(s); ss = warp_sum(ss);
    if (lane == 0) { sh1[wid] = s; sh2[wid] = ss; }
    __syncthreads();
    if (wid == 0) {
        s  = (lane < 8) ? sh1[lane] : 0.f;
        ss = (lane < 8) ? sh2[lane] : 0.f;
        s = warp_sum(s); ss = warp_sum(ss);
        if (lane == 0) { sh1[0] = s; sh2[0] = ss; }
    }
    __syncthreads();
    const float inv_n = 1.f / (float)(CPG * LDIM);
    const float mean = sh1[0] * inv_n;
    const float var  = sh2[0] * inv_n - mean * mean;
    const float rstd = rsqrtf(var + GN_EPS);
    if (threadIdx.x < CPG) {
        float sc = gamma[g * CPG + threadIdx.x] * rstd;
        scg[threadIdx.x] = sc;
        sbg[threadIdx.x] = beta[g * CPG + threadIdx.x] - mean * sc;
    }
    __syncthreads();

    __shared__ float tile[CPG][133];
    for (int l0 = 0; l0 < LDIM; l0 += 128) {
        for (int it = threadIdx.x; it < 512; it += 256) {
            int c  = it >> 5;
            int l4 = (it & 31) * 4;
            float4 t = *reinterpret_cast<const float4*>(&x[base + (size_t)c * LDIM + l0 + l4]);
            float sc = scg[c], sb = sbg[c];
            tile[c][l4 + 0] = t.x * sc + sb;
            tile[c][l4 + 1] = t.y * sc + sb;
            tile[c][l4 + 2] = t.z * sc + sb;
            tile[c][l4 + 3] = t.w * sc + sb;
        }
        __syncthreads();
        for (int it = threadIdx.x; it < 512; it += 256) {
            int l  = it >> 2;
            int c4 = (it & 3) * 4;
            __half2* dst = reinterpret_cast<__half2*>(
                ht + ((size_t)b * LDIM + l0 + l) * CDIM + g * CPG + c4);
            dst[0] = __floats2half2_rn(tile[c4 + 0][l], tile[c4 + 1][l]);
            dst[1] = __floats2half2_rn(tile[c4 + 2][l], tile[c4 + 3][l]);
        }
        __syncthreads();
    }
}

// ============================================================================
// fp16 tensor-core GEMM: D[m,n] = sum_k A[m,k]*B[n,k]  (A:[M,K], B:[N,K] fp16)
// CTA: 128 thr (4 warps), 128x128 tile, warp tile 64x64 (2x2 warp grid).
// K-chunk 64 halves (128B rows), 3-stage cp.async, XOR swizzle on 16B granules.
// EPI: 0 = fp16 out           1 = fp16 out + bias[n]
//      2 = fp16 transposed D[n*ldc+m] + bias[n]
//      3 = fp32 out * alpha   4 = fp32 out + bias[m] + resid[m*ldc+n]
// ============================================================================
#define STAGE_BYTES 32768   // A 16KB + B 16KB
#define GEMM_SMEM   (3 * STAGE_BYTES)

// byte offset of half (row, k) inside a 128-row x 64-half tile
#define FRAG_OFF(row, k) \
    ((row) * 128 + (((((k) >> 3) ^ (row)) & 7) << 4) + (((k) & 7) << 1))

template<int EPI>
__global__ __launch_bounds__(128, 2)
void gemm_h(const __half* __restrict__ A, const __half* __restrict__ B,
            void* __restrict__ Dv, int K, int lda, int ldb, int ldc,
            long long sA, long long sB, long long sD,
            const float* __restrict__ bias, float alpha,
            const float* __restrict__ resid) {
    extern __shared__ char smem[];
    const uint32_t sb = (uint32_t)__cvta_generic_to_shared(smem);
    const int tid = threadIdx.x;
    const int lane = tid & 31;
    const int warp = tid >> 5;
    const int gid = lane >> 2;   // 0..7
    const int tig = lane & 3;    // 0..3
    const int wm = warp & 1;     // m half
    const int wn = warp >> 1;    // n half
    const int m0 = blockIdx.y * 128;
    const int n0 = blockIdx.x * 128;
    const int bz = blockIdx.z;

    A += (long long)bz * sA;
    B += (long long)bz * sB;

    // loader geometry: rows lm + u*16 (u=0..7), 16B granule lg (8 halves)
    const int lm = tid >> 3;          // 0..15
    const int lg = tid & 7;           // 0..7
    const __half* Ap = A + (long long)(m0 + lm) * lda + lg * 8;
    const __half* Bp = B + (long long)(n0 + lm) * ldb + lg * 8;
    const uint32_t sts_off = (uint32_t)(lm * 128 + (((lg ^ lm) & 7) << 4));

    const int nch = K / 64;

#define ISSUE_STAGE(st, buf) do {                                             \
        const uint32_t d0 = sb + (uint32_t)(buf) * STAGE_BYTES + sts_off;     \
        const __half* ap = Ap + (st) * 64;                                    \
        const __half* bp = Bp + (st) * 64;                                    \
        _Pragma("unroll")                                                     \
        for (int u = 0; u < 8; u++)                                           \
            cp_async16(d0 + u * 2048, ap + (long long)u * 16 * lda);          \
        _Pragma("unroll")                                                     \
        for (int u = 0; u < 8; u++)                                           \
            cp_async16(d0 + 16384 + u * 2048, bp + (long long)u * 16 * ldb);  \
    } while (0)

    ISSUE_STAGE(0, 0); cp_commit();
    ISSUE_STAGE(1, 1); cp_commit();

    float acc[4][8][4];
#pragma unroll
    for (int i = 0; i < 4; i++)
#pragma unroll
        for (int j = 0; j < 8; j++)
#pragma unroll
            for (int r = 0; r < 4; r++) acc[i][j][r] = 0.f;

    for (int i = 0; i < nch; i++) {
        cp_wait<1>();
        __syncthreads();
        if (i + 2 < nch) ISSUE_STAGE(i + 2, (i + 2) % 3);
        cp_commit();

        const char* Asb = smem + (i % 3) * STAGE_BYTES;
        const char* Bsb = Asb + 16384;
#pragma unroll
        for (int ks = 0; ks < 4; ks++) {
            const int kk = ks * 16;
            const int k0 = kk + 2 * tig;
            uint32_t afr[4][4], bfr[8][2];
#pragma unroll
            for (int mt = 0; mt < 4; mt++) {
                const int r = wm * 64 + mt * 16 + gid;
                afr[mt][0] = *reinterpret_cast<const uint32_t*>(Asb + FRAG_OFF(r,     k0));
                afr[mt][1] = *reinterpret_cast<const uint32_t*>(Asb + FRAG_OFF(r + 8, k0));
                afr[mt][2] = *reinterpret_cast<const uint32_t*>(Asb + FRAG_OFF(r,     k0 + 8));
                afr[mt][3] = *reinterpret_cast<const uint32_t*>(Asb + FRAG_OFF(r + 8, k0 + 8));
            }
#pragma unroll
            for (int nt = 0; nt < 8; nt++) {
                const int r = wn * 64 + nt * 8 + gid;
                bfr[nt][0] = *reinterpret_cast<const uint32_t*>(Bsb + FRAG_OFF(r, k0));
                bfr[nt][1] = *reinterpret_cast<const uint32_t*>(Bsb + FRAG_OFF(r, k0 + 8));
            }
#pragma unroll
            for (int mt = 0; mt < 4; mt++)
#pragma unroll
                for (int nt = 0; nt < 8; nt++)
                    mma_f16(acc[mt][nt], afr[mt], bfr[nt]);
        }
    }
#undef ISSUE_STAGE

    // epilogue
#pragma unroll
    for (int mt = 0; mt < 4; mt++) {
        const int m = m0 + wm * 64 + mt * 16 + gid;
#pragma unroll
        for (int nt = 0; nt < 8; nt++) {
            const int n = n0 + wn * 64 + nt * 8 + tig * 2;
            float* c = acc[mt][nt];
            if (EPI == 0 || EPI == 1) {
                __half* Dh = (__half*)Dv + (long long)bz * sD;
                float b0v = 0.f, b1v = 0.f;
                if (EPI == 1) { b0v = bias[n]; b1v = bias[n + 1]; }
                *reinterpret_cast<__half2*>(Dh + (long long)m * ldc + n) =
                    __floats2half2_rn(c[0] + b0v, c[1] + b1v);
                *reinterpret_cast<__half2*>(Dh + (long long)(m + 8) * ldc + n) =
                    __floats2half2_rn(c[2] + b0v, c[3] + b1v);
            } else if (EPI == 2) {
                __half* Dh = (__half*)Dv + (long long)bz * sD;
                const float b0v = bias[n], b1v = bias[n + 1];
                Dh[(long long)n * ldc + m]           = __float2half(c[0] + b0v);
                Dh[(long long)(n + 1) * ldc + m]     = __float2half(c[1] + b1v);
                Dh[(long long)n * ldc + m + 8]       = __float2half(c[2] + b0v);
                Dh[(long long)(n + 1) * ldc + m + 8] = __float2half(c[3] + b1v);
            } else if (EPI == 3) {
                float* Df = (float*)Dv + (long long)bz * sD;
                *reinterpret_cast<float2*>(&Df[(long long)m * ldc + n]) =
                    make_float2(c[0] * alpha, c[1] * alpha);
                *reinterpret_cast<float2*>(&Df[(long long)(m + 8) * ldc + n]) =
                    make_float2(c[2] * alpha, c[3] * alpha);
            } else {  // EPI == 4
                float* Df = (float*)Dv + (long long)bz * sD;
                const float* rs = resid + (long long)bz * sD;
                const float bm0 = bias[m], bm1 = bias[m + 8];
                const float2 r0 = *reinterpret_cast<const float2*>(
                    &rs[(long long)m * ldc + n]);
                const float2 r1 = *reinterpret_cast<const float2*>(
                    &rs[(long long)(m + 8) * ldc + n]);
                *reinterpret_cast<float2*>(&Df[(long long)m * ldc + n]) =
                    make_float2(c[0] + bm0 + r0.x, c[1] + bm0 + r0.y);
                *reinterpret_cast<float2*>(&Df[(long long)(m + 8) * ldc + n]) =
                    make_float2(c[2] + bm1 + r1.x, c[3] + bm1 + r1.y);
            }
        }
    }
}

// ============================================================================
// Row softmax over L=2048: read fp32 S, write fp16 P
// ============================================================================
__global__ __launch_bounds__(256)
void softmax_kernel(const float* __restrict__ S, __half* __restrict__ P) {
    const float4* row = reinterpret_cast<const float4*>(S + (size_t)blockIdx.x * LDIM);
    __half2* prow = reinterpret_cast<__half2*>(P + (size_t)blockIdx.x * LDIM);
    const int t = threadIdx.x;
    float4 v0 = row[t];
    float4 v1 = row[t + 256];

    float m = fmaxf(fmaxf(fmaxf(v0.x, v0.y), fmaxf(v0.z, v0.w)),
                    fmaxf(fmaxf(v1.x, v1.y), fmaxf(v1.z, v1.w)));
    __shared__ float sh[8];
    int lane = t & 31, wid = t >> 5;
    m = warp_max(m);
    if (lane == 0) sh[wid] = m;
    __syncthreads();
    if (wid == 0) {
        float mm = (lane < 8) ? sh[lane] : -3.4e38f;
        mm = warp_max(mm);
        if (lane == 0) sh[0] = mm;
    }
    __syncthreads();
    m = sh[0];
    __syncthreads();

    v0.x = __expf(v0.x - m); v0.y = __expf(v0.y - m);
    v0.z = __expf(v0.z - m); v0.w = __expf(v0.w - m);
    v1.x = __expf(v1.x - m); v1.y = __expf(v1.y - m);
    v1.z = __expf(v1.z - m); v1.w = __expf(v1.w - m);

    float s = v0.x + v0.y + v0.z + v0.w + v1.x + v1.y + v1.z + v1.w;
    s = warp_sum(s);
    if (lane == 0) sh[wid] = s;
    __syncthreads();
    if (wid == 0) {
        float t2 = (lane < 8) ? sh[lane] : 0.f;
        t2 = warp_sum(t2);
        if (lane == 0) sh[0] = t2;
    }
    __syncthreads();
    const float inv = 1.f / sh[0];

    prow[2 * t]             = __floats2half2_rn(v0.x * inv, v0.y * inv);
    prow[2 * t + 1]         = __floats2half2_rn(v0.z * inv, v0.w * inv);
    prow[2 * (t + 256)]     = __floats2half2_rn(v1.x * inv, v1.y * inv);
    prow[2 * (t + 256) + 1] = __floats2half2_rn(v1.z * inv, v1.w * inv);
}

// ============================================================================
// Launch
// ============================================================================
extern "C" void kernel_launch(void* const* d_in, const int* in_sizes, int n_in,
                              void* d_out, int out_size) {
    (void)in_sizes; (void)n_in; (void)out_size;
    const float* x   = (const float*)d_in[0];
    const float* gns = (const float*)d_in[1];
    const float* gnb = (const float*)d_in[2];
    const float* wq  = (const float*)d_in[3];
    const float* bq  = (const float*)d_in[4];
    const float* wk  = (const float*)d_in[5];
    const float* bk  = (const float*)d_in[6];
    const float* wv  = (const float*)d_in[7];
    const float* bv  = (const float*)d_in[8];
    const float* wo  = (const float*)d_in[9];
    const float* bo  = (const float*)d_in[10];
    float* out = (float*)d_out;

    unsigned char* base = nullptr;
    cudaGetSymbolAddress((void**)&base, g_scratch);
    __half* ht  = (__half*)(base);
    __half* qh  = (__half*)(base + 16777216);
    __half* kh  = (__half*)(base + 33554432);
    __half* vTh = (__half*)(base + 50331648);
    __half* ah  = (__half*)(base + 67108864);
    float*  s   = (float*)(base + 83886080);
    __half* p   = (__half*)(base + 218103808);
    __half* wh  = (__half*)(base + 285212672);
    __half* wqh = wh;
    __half* wkh = wh + 262144;
    __half* wvh = wh + 524288;
    __half* woh = wh + 786432;

    const float attn_scale = 0.044194173824159216f;  // 512^-0.5

    static bool attr_done = false;
    if (!attr_done) {
        cudaFuncSetAttribute(gemm_h<0>, cudaFuncAttributeMaxDynamicSharedMemorySize, GEMM_SMEM);
        cudaFuncSetAttribute(gemm_h<1>, cudaFuncAttributeMaxDynamicSharedMemorySize, GEMM_SMEM);
        cudaFuncSetAttribute(gemm_h<2>, cudaFuncAttributeMaxDynamicSharedMemorySize, GEMM_SMEM);
        cudaFuncSetAttribute(gemm_h<3>, cudaFuncAttributeMaxDynamicSharedMemorySize, GEMM_SMEM);
        cudaFuncSetAttribute(gemm_h<4>, cudaFuncAttributeMaxDynamicSharedMemorySize, GEMM_SMEM);
        attr_done = true;
    }

    // 0) Weights -> fp16 (independent of GN)
    conv_w_kernel<<<4096, 256>>>(wq, wk, wv, wo, wh);

    // 1) GroupNorm + transpose: ht [B, L, C] fp16
    gn_t_kernel<<<BDIM * NGRP, 256>>>(x, gns, gnb, ht);

    // 2) QKV projections (M=L, N=C, K=C); V written transposed as vT [C, L]
    {
        dim3 grid(CDIM / 128, LDIM / 128, BDIM);
        gemm_h<1><<<grid, 128, GEMM_SMEM>>>(ht, wqh, qh, CDIM, CDIM, CDIM, CDIM,
            CL, 0, CL, bq, 0.f, nullptr);
        gemm_h<1><<<grid, 128, GEMM_SMEM>>>(ht, wkh, kh, CDIM, CDIM, CDIM, CDIM,
            CL, 0, CL, bk, 0.f, nullptr);
        gemm_h<2><<<grid, 128, GEMM_SMEM>>>(ht, wvh, vTh, CDIM, CDIM, CDIM, LDIM,
            CL, 0, CL, bv, 0.f, nullptr);
    }

    // 3) Scores: s[i,j] = scale * q[i,:].k[j,:]  (M=N=L, K=C, fp32 out)
    {
        dim3 grid(LDIM / 128, LDIM / 128, BDIM);
        gemm_h<3><<<grid, 128, GEMM_SMEM>>>(qh, kh, s, CDIM, CDIM, CDIM, LDIM,
            CL, CL, LL, nullptr, attn_scale, nullptr);
    }

    // 4) Softmax rows: s fp32 -> p fp16
    softmax_kernel<<<BDIM * LDIM, 256>>>(s, p);

    // 5) a[i,c] = sum_j p[i,j] * vT[c,j]  (M=L, N=C, K=L, fp16 out)
    {
        dim3 grid(CDIM / 128, LDIM / 128, BDIM);
        gemm_h<0><<<grid, 128, GEMM_SMEM>>>(p, vTh, ah, LDIM, LDIM, LDIM, CDIM,
            LL, CL, CL, nullptr, 0.f, nullptr);
    }

    // 6) out[o,l] = sum_c wo[o,c] * a[l,c] + bo[o] + x[o,l]  (M=C, N=L, fp32 out)
    {
        dim3 grid(LDIM / 128, CDIM / 128, BDIM);
        gemm_h<4><<<grid, 128, GEMM_SMEM>>>(woh, ah, out, CDIM, CDIM, CDIM, LDIM,
            0, CL, CL, bo, 0.f, x);
    }
}

// round 8
// speedup vs baseline: 7.7257x; 1.0476x over previous
#include <cuda_runtime.h>
#include <cuda_fp16.h>
#include <cstdint>

// Problem: x [B=8, C=512, L=2048], GroupNorm(32) -> QKV -> attention -> O-proj + residual.
#define BDIM 8
#define CDIM 512
#define LDIM 2048
#define NGRP 32
#define CPG  (CDIM / NGRP)   // 16
#define GN_EPS 1e-5f

#define CL 1048576LL   // C*L per-batch elems
#define LL 4194304LL   // L*L per-batch elems

// Scratch (bytes):
//  ht  [B,L,C] fp16 @ 0          (16,777,216)
//  qh  [B,L,C] fp16 @ 16777216
//  kh  [B,L,C] fp16 @ 33554432
//  vTh [B,C,L] fp16 @ 50331648
//  ah  [B,L,C] fp16 @ 67108864
//  s   [B,L,L] fp32 @ 83886080   (134,217,728)
//  p   [B,L,L] fp16 @ 218103808  (67,108,864)
//  wh  4x[C,C] fp16 @ 285212672  (wq|wk|wv stacked = [3C,C], then wo)
__device__ __align__(256) unsigned char g_scratch[287309824];

// ---------------------------------------------------------------------------
__device__ __forceinline__ float warp_sum(float v) {
#pragma unroll
    for (int o = 16; o > 0; o >>= 1) v += __shfl_xor_sync(0xFFFFFFFFu, v, o);
    return v;
}
__device__ __forceinline__ float warp_max(float v) {
#pragma unroll
    for (int o = 16; o > 0; o >>= 1) v = fmaxf(v, __shfl_xor_sync(0xFFFFFFFFu, v, o));
    return v;
}
// fp16 MMA, fp32 accumulate: D[16x8] += A[16x16] * B[16x8]
__device__ __forceinline__ void mma_f16(float* c, const uint32_t* a, const uint32_t* b) {
    asm volatile(
        "mma.sync.aligned.m16n8k16.row.col.f32.f16.f16.f32 "
        "{%0,%1,%2,%3}, {%4,%5,%6,%7}, {%8,%9}, {%0,%1,%2,%3};"
        : "+f"(c[0]), "+f"(c[1]), "+f"(c[2]), "+f"(c[3])
        : "r"(a[0]), "r"(a[1]), "r"(a[2]), "r"(a[3]), "r"(b[0]), "r"(b[1]));
}
__device__ __forceinline__ void ldsm_x4(uint32_t& r0, uint32_t& r1, uint32_t& r2,
                                        uint32_t& r3, uint32_t addr) {
    asm volatile("ldmatrix.sync.aligned.m8n8.x4.shared.b16 {%0,%1,%2,%3}, [%4];"
                 : "=r"(r0), "=r"(r1), "=r"(r2), "=r"(r3) : "r"(addr));
}
__device__ __forceinline__ void cp_async16(uint32_t dst, const void* src) {
    asm volatile("cp.async.cg.shared.global [%0], [%1], 16;" :: "r"(dst), "l"(src));
}
__device__ __forceinline__ void cp_commit() {
    asm volatile("cp.async.commit_group;" ::: "memory");
}
template<int N>
__device__ __forceinline__ void cp_wait() {
    asm volatile("cp.async.wait_group %0;" :: "n"(N) : "memory");
}

// ============================================================================
// Weight convert: 4 x [C,C] fp32 -> fp16 (wq | wk | wv | wo stacked)
// ============================================================================
__global__ __launch_bounds__(256)
void conv_w_kernel(const float* __restrict__ wq, const float* __restrict__ wk,
                   const float* __restrict__ wv, const float* __restrict__ wo,
                   __half* __restrict__ dst) {
    int i = blockIdx.x * 256 + threadIdx.x;
    int which = i >> 18;
    int off = i & 0x3FFFF;
    const float* src = (which == 0) ? wq : (which == 1) ? wk : (which == 2) ? wv : wo;
    dst[i] = __float2half(src[off]);
}

// ============================================================================
// GroupNorm fused with transpose: x [B,C,L] fp32 -> ht [B,L,C] fp16
// ============================================================================
__global__ __launch_bounds__(256)
void gn_t_kernel(const float* __restrict__ x, const float* __restrict__ gamma,
                 const float* __restrict__ beta, __half* __restrict__ ht) {
    const int b = blockIdx.x / NGRP;
    const int g = blockIdx.x % NGRP;
    const size_t base = ((size_t)b * CDIM + (size_t)g * CPG) * LDIM;
    const float4* xp = reinterpret_cast<const float4*>(x + base);

    const int n4 = CPG * LDIM / 4;  // 8192
    float s = 0.f, ss = 0.f;
    for (int i = threadIdx.x; i < n4; i += 256) {
        float4 t = xp[i];
        s  += t.x + t.y + t.z + t.w;
        ss += t.x * t.x + t.y * t.y + t.z * t.z + t.w * t.w;
    }
    __shared__ float sh1[8], sh2[8];
    __shared__ float scg[CPG], sbg[CPG];
    int lane = threadIdx.x & 31, wid = threadIdx.x >> 5;
    s = warp_sum(s); ss = warp_sum(ss);
    if (lane == 0) { sh1[wid] = s; sh2[wid] = ss; }
    __syncthreads();
    if (wid == 0) {
        s  = (lane < 8) ? sh1[lane] : 0.f;
        ss = (lane < 8) ? sh2[lane] : 0.f;
        s = warp_sum(s); ss = warp_sum(ss);
        if (lane == 0) { sh1[0] = s; sh2[0] = ss; }
    }
    __syncthreads();
    const float inv_n = 1.f / (float)(CPG * LDIM);
    const float mean = sh1[0] * inv_n;
    const float var  = sh2[0] * inv_n - mean * mean;
    const float rstd = rsqrtf(var + GN_EPS);
    if (threadIdx.x < CPG) {
        float sc = gamma[g * CPG + threadIdx.x] * rstd;
        scg[threadIdx.x] = sc;
        sbg[threadIdx.x] = beta[g * CPG + threadIdx.x] - mean * sc;
    }
    __syncthreads();

    __shared__ float tile[CPG][133];
    for (int l0 = 0; l0 < LDIM; l0 += 128) {
        for (int it = threadIdx.x; it < 512; it += 256) {
            int c  = it >> 5;
            int l4 = (it & 31) * 4;
            float4 t = *reinterpret_cast<const float4*>(&x[base + (size_t)c * LDIM + l0 + l4]);
            float sc = scg[c], sb = sbg[c];
            tile[c][l4 + 0] = t.x * sc + sb;
            tile[c][l4 + 1] = t.y * sc + sb;
            tile[c][l4 + 2] = t.z * sc + sb;
            tile[c][l4 + 3] = t.w * sc + sb;
        }
        __syncthreads();
        for (int it = threadIdx.x; it < 512; it += 256) {
            int l  = it >> 2;
            int c4 = (it & 3) * 4;
            __half2* dst = reinterpret_cast<__half2*>(
                ht + ((size_t)b * LDIM + l0 + l) * CDIM + g * CPG + c4);
            dst[0] = __floats2half2_rn(tile[c4 + 0][l], tile[c4 + 1][l]);
            dst[1] = __floats2half2_rn(tile[c4 + 2][l], tile[c4 + 3][l]);
        }
        __syncthreads();
    }
}

// ============================================================================
// fp16 tensor-core GEMM: D[m,n] = sum_k A[m,k]*B[n,k]  (A:[M,K], B:[N,K] fp16)
// CTA: 128 thr (4 warps), 128x128 tile, warp tile 64x64 (2x2 warp grid).
// K-chunk 64 halves, 3-stage cp.async, XOR swizzle, ldmatrix fragment loads.
// EPI: 0 = fp16 out           1 = fp16 out + bias[n]
//      3 = fp32 out * alpha   4 = fp32 out + bias[m] + resid[m*ldc+n]
//      5 = merged QKV routing: n in [0,512)->q(+bias), [512,1024)->k(+bias2),
//          [1024,1536)->vT transposed (+bias3)
// ============================================================================
#define STAGE_BYTES 32768   // A 16KB + B 16KB
#define GEMM_SMEM   (3 * STAGE_BYTES)

template<int EPI>
__global__ __launch_bounds__(128, 2)
void gemm_h(const __half* __restrict__ A, const __half* __restrict__ B,
            void* __restrict__ Dv, int K, int lda, int ldb, int ldc,
            long long sA, long long sB, long long sD,
            const float* __restrict__ bias, float alpha,
            const float* __restrict__ resid,
            void* __restrict__ Dv2, void* __restrict__ Dv3,
            const float* __restrict__ bias2, const float* __restrict__ bias3) {
    extern __shared__ char smem[];
    const uint32_t sb = (uint32_t)__cvta_generic_to_shared(smem);
    const int tid = threadIdx.x;
    const int lane = tid & 31;
    const int warp = tid >> 5;
    const int gid = lane >> 2;   // 0..7
    const int tig = lane & 3;    // 0..3
    const int wm = warp & 1;     // m half
    const int wn = warp >> 1;    // n half
    const int m0 = blockIdx.y * 128;
    const int n0 = blockIdx.x * 128;
    const int bz = blockIdx.z;

    A += (long long)bz * sA;
    B += (long long)bz * sB;

    // ---- cp.async loader geometry: rows lm + u*16, 16B granule lg
    const int lm = tid >> 3;          // 0..15
    const int lg = tid & 7;           // 0..7
    const __half* Ap = A + (long long)(m0 + lm) * lda + lg * 8;
    const __half* Bp = B + (long long)(n0 + lm) * ldb + lg * 8;
    const uint32_t sts_off = (uint32_t)(lm * 128 + (((lg ^ lm) & 7) << 4));

    // ---- ldmatrix geometry
    const int r7 = lane & 7;
    const int lhi = lane >> 4;              // A: k+8 selector
    const int arow = ((lane >> 3) & 1) * 8 + r7;   // 0..15 within 16-row frag
    const int bhi = (lane >> 3) & 1;        // B: k+8 selector
    const int brow = ((lane >> 4) & 1) * 8 + r7;   // 0..15 within 16-row pair
    uint32_t aRowOff[4], bRowOff[4];
#pragma unroll
    for (int mt = 0; mt < 4; mt++)
        aRowOff[mt] = (uint32_t)((wm * 64 + mt * 16 + arow) * 128);
#pragma unroll
    for (int j = 0; j < 4; j++)
        bRowOff[j] = (uint32_t)((wn * 64 + j * 16 + brow) * 128) + 16384u;

    const int nch = K / 64;

#define ISSUE_STAGE(st, buf) do {                                             \
        const uint32_t d0 = sb + (uint32_t)(buf) * STAGE_BYTES + sts_off;     \
        const __half* ap = Ap + (st) * 64;                                    \
        const __half* bp = Bp + (st) * 64;                                    \
        _Pragma("unroll")                                                     \
        for (int u = 0; u < 8; u++)                                           \
            cp_async16(d0 + u * 2048, ap + (long long)u * 16 * lda);          \
        _Pragma("unroll")                                                     \
        for (int u = 0; u < 8; u++)                                           \
            cp_async16(d0 + 16384 + u * 2048, bp + (long long)u * 16 * ldb);  \
    } while (0)

    ISSUE_STAGE(0, 0); cp_commit();
    ISSUE_STAGE(1, 1); cp_commit();

    float acc[4][8][4];
#pragma unroll
    for (int i = 0; i < 4; i++)
#pragma unroll
        for (int j = 0; j < 8; j++)
#pragma unroll
            for (int r = 0; r < 4; r++) acc[i][j][r] = 0.f;

    for (int i = 0; i < nch; i++) {
        cp_wait<1>();
        __syncthreads();
        if (i + 2 < nch) ISSUE_STAGE(i + 2, (i + 2) % 3);
        cp_commit();

        const uint32_t stage = sb + (uint32_t)(i % 3) * STAGE_BYTES;
#pragma unroll
        for (int ks = 0; ks < 4; ks++) {
            const uint32_t swa = (uint32_t)((((2 * ks + lhi) ^ r7) & 7) << 4);
            const uint32_t swb = (uint32_t)((((2 * ks + bhi) ^ r7) & 7) << 4);
            uint32_t afr[4][4], bfr[8][2];
#pragma unroll
            for (int mt = 0; mt < 4; mt++)
                ldsm_x4(afr[mt][0], afr[mt][1], afr[mt][2], afr[mt][3],
                        stage + aRowOff[mt] + swa);
#pragma unroll
            for (int j = 0; j < 4; j++)
                ldsm_x4(bfr[2 * j][0], bfr[2 * j][1], bfr[2 * j + 1][0],
                        bfr[2 * j + 1][1], stage + bRowOff[j] + swb);
#pragma unroll
            for (int mt = 0; mt < 4; mt++)
#pragma unroll
                for (int nt = 0; nt < 8; nt++)
                    mma_f16(acc[mt][nt], afr[mt], bfr[nt]);
        }
    }
#undef ISSUE_STAGE

    // epilogue
#pragma unroll
    for (int mt = 0; mt < 4; mt++) {
        const int m = m0 + wm * 64 + mt * 16 + gid;
#pragma unroll
        for (int nt = 0; nt < 8; nt++) {
            const int n = n0 + wn * 64 + nt * 8 + tig * 2;
            float* c = acc[mt][nt];
            if (EPI == 0 || EPI == 1) {
                __half* Dh = (__half*)Dv + (long long)bz * sD;
                float b0v = 0.f, b1v = 0.f;
                if (EPI == 1) { b0v = bias[n]; b1v = bias[n + 1]; }
                *reinterpret_cast<__half2*>(Dh + (long long)m * ldc + n) =
                    __floats2half2_rn(c[0] + b0v, c[1] + b1v);
                *reinterpret_cast<__half2*>(Dh + (long long)(m + 8) * ldc + n) =
                    __floats2half2_rn(c[2] + b0v, c[3] + b1v);
            } else if (EPI == 3) {
                float* Df = (float*)Dv + (long long)bz * sD;
                *reinterpret_cast<float2*>(&Df[(long long)m * ldc + n]) =
                    make_float2(c[0] * alpha, c[1] * alpha);
                *reinterpret_cast<float2*>(&Df[(long long)(m + 8) * ldc + n]) =
                    make_float2(c[2] * alpha, c[3] * alpha);
            } else if (EPI == 4) {
                float* Df = (float*)Dv + (long long)bz * sD;
                const float* rs = resid + (long long)bz * sD;
                const float bm0 = bias[m], bm1 = bias[m + 8];
                const float2 r0 = *reinterpret_cast<const float2*>(
                    &rs[(long long)m * ldc + n]);
                const float2 r1 = *reinterpret_cast<const float2*>(
                    &rs[(long long)(m + 8) * ldc + n]);
                *reinterpret_cast<float2*>(&Df[(long long)m * ldc + n]) =
                    make_float2(c[0] + bm0 + r0.x, c[1] + bm0 + r0.y);
                *reinterpret_cast<float2*>(&Df[(long long)(m + 8) * ldc + n]) =
                    make_float2(c[2] + bm1 + r1.x, c[3] + bm1 + r1.y);
            } else {  // EPI == 5: merged QKV routing
                const int which = n >> 9;          // 0=q, 1=k, 2=v
                const int nl = n & 511;
                if (which < 2) {
                    __half* Dh = ((which == 0) ? (__half*)Dv : (__half*)Dv2)
                                 + (long long)bz * CL;
                    const float* bb = (which == 0) ? bias : bias2;
                    const float b0v = bb[nl], b1v = bb[nl + 1];
                    *reinterpret_cast<__half2*>(Dh + (long long)m * CDIM + nl) =
                        __floats2half2_rn(c[0] + b0v, c[1] + b1v);
                    *reinterpret_cast<__half2*>(Dh + (long long)(m + 8) * CDIM + nl) =
                        __floats2half2_rn(c[2] + b0v, c[3] + b1v);
                } else {
                    __half* Dh = (__half*)Dv3 + (long long)bz * CL;
                    const float b0v = bias3[nl], b1v = bias3[nl + 1];
                    Dh[(long long)nl * LDIM + m]           = __float2half(c[0] + b0v);
                    Dh[(long long)(nl + 1) * LDIM + m]     = __float2half(c[1] + b1v);
                    Dh[(long long)nl * LDIM + m + 8]       = __float2half(c[2] + b0v);
                    Dh[(long long)(nl + 1) * LDIM + m + 8] = __float2half(c[3] + b1v);
                }
            }
        }
    }
}

// ============================================================================
// Row softmax over L=2048: read fp32 S, write fp16 P
// ============================================================================
__global__ __launch_bounds__(256)
void softmax_kernel(const float* __restrict__ S, __half* __restrict__ P) {
    const float4* row = reinterpret_cast<const float4*>(S + (size_t)blockIdx.x * LDIM);
    __half2* prow = reinterpret_cast<__half2*>(P + (size_t)blockIdx.x * LDIM);
    const int t = threadIdx.x;
    float4 v0 = row[t];
    float4 v1 = row[t + 256];

    float m = fmaxf(fmaxf(fmaxf(v0.x, v0.y), fmaxf(v0.z, v0.w)),
                    fmaxf(fmaxf(v1.x, v1.y), fmaxf(v1.z, v1.w)));
    __shared__ float sh[8];
    int lane = t & 31, wid = t >> 5;
    m = warp_max(m);
    if (lane == 0) sh[wid] = m;
    __syncthreads();
    if (wid == 0) {
        float mm = (lane < 8) ? sh[lane] : -3.4e38f;
        mm = warp_max(mm);
        if (lane == 0) sh[0] = mm;
    }
    __syncthreads();
    m = sh[0];
    __syncthreads();

    v0.x = __expf(v0.x - m); v0.y = __expf(v0.y - m);
    v0.z = __expf(v0.z - m); v0.w = __expf(v0.w - m);
    v1.x = __expf(v1.x - m); v1.y = __expf(v1.y - m);
    v1.z = __expf(v1.z - m); v1.w = __expf(v1.w - m);

    float s = v0.x + v0.y + v0.z + v0.w + v1.x + v1.y + v1.z + v1.w;
    s = warp_sum(s);
    if (lane == 0) sh[wid] = s;
    __syncthreads();
    if (wid == 0) {
        float t2 = (lane < 8) ? sh[lane] : 0.f;
        t2 = warp_sum(t2);
        if (lane == 0) sh[0] = t2;
    }
    __syncthreads();
    const float inv = 1.f / sh[0];

    prow[2 * t]             = __floats2half2_rn(v0.x * inv, v0.y * inv);
    prow[2 * t + 1]         = __floats2half2_rn(v0.z * inv, v0.w * inv);
    prow[2 * (t + 256)]     = __floats2half2_rn(v1.x * inv, v1.y * inv);
    prow[2 * (t + 256) + 1] = __floats2half2_rn(v1.z * inv, v1.w * inv);
}

// ============================================================================
// Launch
// ============================================================================
extern "C" void kernel_launch(void* const* d_in, const int* in_sizes, int n_in,
                              void* d_out, int out_size) {
    (void)in_sizes; (void)n_in; (void)out_size;
    const float* x   = (const float*)d_in[0];
    const float* gns = (const float*)d_in[1];
    const float* gnb = (const float*)d_in[2];
    const float* wq  = (const float*)d_in[3];
    const float* bq  = (const float*)d_in[4];
    const float* wk  = (const float*)d_in[5];
    const float* bk  = (const float*)d_in[6];
    const float* wv  = (const float*)d_in[7];
    const float* bv  = (const float*)d_in[8];
    const float* wo  = (const float*)d_in[9];
    const float* bo  = (const float*)d_in[10];
    float* out = (float*)d_out;

    unsigned char* base = nullptr;
    cudaGetSymbolAddress((void**)&base, g_scratch);
    __half* ht  = (__half*)(base);
    __half* qh  = (__half*)(base + 16777216);
    __half* kh  = (__half*)(base + 33554432);
    __half* vTh = (__half*)(base + 50331648);
    __half* ah  = (__half*)(base + 67108864);
    float*  s   = (float*)(base + 83886080);
    __half* p   = (__half*)(base + 218103808);
    __half* wh  = (__half*)(base + 285212672);   // [wq|wk|wv] stacked, then wo
    __half* woh = wh + 786432;

    const float attn_scale = 0.044194173824159216f;  // 512^-0.5

    static bool attr_done = false;
    if (!attr_done) {
        cudaFuncSetAttribute(gemm_h<0>, cudaFuncAttributeMaxDynamicSharedMemorySize, GEMM_SMEM);
        cudaFuncSetAttribute(gemm_h<3>, cudaFuncAttributeMaxDynamicSharedMemorySize, GEMM_SMEM);
        cudaFuncSetAttribute(gemm_h<4>, cudaFuncAttributeMaxDynamicSharedMemorySize, GEMM_SMEM);
        cudaFuncSetAttribute(gemm_h<5>, cudaFuncAttributeMaxDynamicSharedMemorySize, GEMM_SMEM);
        attr_done = true;
    }

    // 0) Weights -> fp16 (wq|wk|wv stacked = [3C, C], then wo)
    conv_w_kernel<<<4096, 256>>>(wq, wk, wv, wo, wh);

    // 1) GroupNorm + transpose: ht [B, L, C] fp16
    gn_t_kernel<<<BDIM * NGRP, 256>>>(x, gns, gnb, ht);

    // 2) Merged QKV projection: M=L, N=3C=1536, K=C; routed epilogue
    {
        dim3 grid(1536 / 128, LDIM / 128, BDIM);
        gemm_h<5><<<grid, 128, GEMM_SMEM>>>(ht, wh, qh, CDIM, CDIM, CDIM, CDIM,
            CL, 0, CL, bq, 0.f, nullptr, kh, vTh, bk, bv);
    }

    // 3) Scores: s[i,j] = scale * q[i,:].k[j,:]  (M=N=L, K=C, fp32 out)
    {
        dim3 grid(LDIM / 128, LDIM / 128, BDIM);
        gemm_h<3><<<grid, 128, GEMM_SMEM>>>(qh, kh, s, CDIM, CDIM, CDIM, LDIM,
            CL, CL, LL, nullptr, attn_scale, nullptr, nullptr, nullptr, nullptr, nullptr);
    }

    // 4) Softmax rows: s fp32 -> p fp16
    softmax_kernel<<<BDIM * LDIM, 256>>>(s, p);

    // 5) a[i,c] = sum_j p[i,j] * vT[c,j]  (M=L, N=C, K=L, fp16 out)
    {
        dim3 grid(CDIM / 128, LDIM / 128, BDIM);
        gemm_h<0><<<grid, 128, GEMM_SMEM>>>(p, vTh, ah, LDIM, LDIM, LDIM, CDIM,
            LL, CL, CL, nullptr, 0.f, nullptr, nullptr, nullptr, nullptr, nullptr);
    }

    // 6) out[o,l] = sum_c wo[o,c] * a[l,c] + bo[o] + x[o,l]  (M=C, N=L, fp32 out)
    {
        dim3 grid(LDIM / 128, CDIM / 128, BDIM);
        gemm_h<4><<<grid, 128, GEMM_SMEM>>>(woh, ah, out, CDIM, CDIM, CDIM, LDIM,
            0, CL, CL, bo, 0.f, x, nullptr, nullptr, nullptr, nullptr);
    }
}

// round 9
// speedup vs baseline: 8.4257x; 1.0906x over previous
#include <cuda_runtime.h>
#include <cuda_fp16.h>
#include <cstdint>

// Problem: x [B=8, C=512, L=2048], GroupNorm(32) -> QKV -> attention -> O-proj + residual.
#define BDIM 8
#define CDIM 512
#define LDIM 2048
#define NGRP 32
#define CPG  (CDIM / NGRP)   // 16
#define GN_EPS 1e-5f
#define EXP_SHIFT 4.0f

#define CL 1048576LL   // C*L per-batch elems
#define LL 4194304LL   // L*L per-batch elems

// Scratch (bytes):
//  ht  [B,L,C] fp16 @ 0
//  qh  [B,L,C] fp16 @ 16777216
//  kh  [B,L,C] fp16 @ 33554432
//  vTh [B,C,L] fp16 @ 50331648
//  ah  [B,L,C] fp16 @ 67108864
//  rsum [B,L] fp32 @ 83886080   (65,536)
//  p   [B,L,L] fp16 @ 218103808 (67,108,864)
//  wh  4x[C,C] fp16 @ 285212672 (wq|wk|wv stacked = [3C,C], then wo)
__device__ __align__(256) unsigned char g_scratch[287309824];

// ---------------------------------------------------------------------------
__device__ __forceinline__ float warp_sum(float v) {
#pragma unroll
    for (int o = 16; o > 0; o >>= 1) v += __shfl_xor_sync(0xFFFFFFFFu, v, o);
    return v;
}
// fp16 MMA, fp32 accumulate: D[16x8] += A[16x16] * B[16x8]
__device__ __forceinline__ void mma_f16(float* c, const uint32_t* a, const uint32_t* b) {
    asm volatile(
        "mma.sync.aligned.m16n8k16.row.col.f32.f16.f16.f32 "
        "{%0,%1,%2,%3}, {%4,%5,%6,%7}, {%8,%9}, {%0,%1,%2,%3};"
        : "+f"(c[0]), "+f"(c[1]), "+f"(c[2]), "+f"(c[3])
        : "r"(a[0]), "r"(a[1]), "r"(a[2]), "r"(a[3]), "r"(b[0]), "r"(b[1]));
}
__device__ __forceinline__ void ldsm_x4(uint32_t& r0, uint32_t& r1, uint32_t& r2,
                                        uint32_t& r3, uint32_t addr) {
    asm volatile("ldmatrix.sync.aligned.m8n8.x4.shared.b16 {%0,%1,%2,%3}, [%4];"
                 : "=r"(r0), "=r"(r1), "=r"(r2), "=r"(r3) : "r"(addr));
}
__device__ __forceinline__ void cp_async16(uint32_t dst, const void* src) {
    asm volatile("cp.async.cg.shared.global [%0], [%1], 16;" :: "r"(dst), "l"(src));
}
__device__ __forceinline__ void cp_commit() {
    asm volatile("cp.async.commit_group;" ::: "memory");
}
template<int N>
__device__ __forceinline__ void cp_wait() {
    asm volatile("cp.async.wait_group %0;" :: "n"(N) : "memory");
}

// ============================================================================
// Weight convert + rsum zero
// ============================================================================
__global__ __launch_bounds__(256)
void conv_w_kernel(const float* __restrict__ wq, const float* __restrict__ wk,
                   const float* __restrict__ wv, const float* __restrict__ wo,
                   __half* __restrict__ dst, float* __restrict__ rsum) {
    int i = blockIdx.x * 256 + threadIdx.x;
    int which = i >> 18;
    int off = i & 0x3FFFF;
    const float* src = (which == 0) ? wq : (which == 1) ? wk : (which == 2) ? wv : wo;
    dst[i] = __float2half(src[off]);
    if (i < BDIM * LDIM) rsum[i] = 0.f;
}

// ============================================================================
// GroupNorm fused with transpose: x [B,C,L] fp32 -> ht [B,L,C] fp16
// ============================================================================
__global__ __launch_bounds__(256)
void gn_t_kernel(const float* __restrict__ x, const float* __restrict__ gamma,
                 const float* __restrict__ beta, __half* __restrict__ ht) {
    const int b = blockIdx.x / NGRP;
    const int g = blockIdx.x % NGRP;
    const size_t base = ((size_t)b * CDIM + (size_t)g * CPG) * LDIM;
    const float4* xp = reinterpret_cast<const float4*>(x + base);

    const int n4 = CPG * LDIM / 4;  // 8192
    float s = 0.f, ss = 0.f;
    for (int i = threadIdx.x; i < n4; i += 256) {
        float4 t = xp[i];
        s  += t.x + t.y + t.z + t.w;
        ss += t.x * t.x + t.y * t.y + t.z * t.z + t.w * t.w;
    }
    __shared__ float sh1[8], sh2[8];
    __shared__ float scg[CPG], sbg[CPG];
    int lane = threadIdx.x & 31, wid = threadIdx.x >> 5;
    s = warp_sum(s); ss = warp_sum(ss);
    if (lane == 0) { sh1[wid] = s; sh2[wid] = ss; }
    __syncthreads();
    if (wid == 0) {
        s  = (lane < 8) ? sh1[lane] : 0.f;
        ss = (lane < 8) ? sh2[lane] : 0.f;
        s = warp_sum(s); ss = warp_sum(ss);
        if (lane == 0) { sh1[0] = s; sh2[0] = ss; }
    }
    __syncthreads();
    const float inv_n = 1.f / (float)(CPG * LDIM);
    const float mean = sh1[0] * inv_n;
    const float var  = sh2[0] * inv_n - mean * mean;
    const float rstd = rsqrtf(var + GN_EPS);
    if (threadIdx.x < CPG) {
        float sc = gamma[g * CPG + threadIdx.x] * rstd;
        scg[threadIdx.x] = sc;
        sbg[threadIdx.x] = beta[g * CPG + threadIdx.x] - mean * sc;
    }
    __syncthreads();

    __shared__ float tile[CPG][133];
    for (int l0 = 0; l0 < LDIM; l0 += 128) {
        for (int it = threadIdx.x; it < 512; it += 256) {
            int c  = it >> 5;
            int l4 = (it & 31) * 4;
            float4 t = *reinterpret_cast<const float4*>(&x[base + (size_t)c * LDIM + l0 + l4]);
            float sc = scg[c], sb = sbg[c];
            tile[c][l4 + 0] = t.x * sc + sb;
            tile[c][l4 + 1] = t.y * sc + sb;
            tile[c][l4 + 2] = t.z * sc + sb;
            tile[c][l4 + 3] = t.w * sc + sb;
        }
        __syncthreads();
        for (int it = threadIdx.x; it < 512; it += 256) {
            int l  = it >> 2;
            int c4 = (it & 3) * 4;
            __half2* dst = reinterpret_cast<__half2*>(
                ht + ((size_t)b * LDIM + l0 + l) * CDIM + g * CPG + c4);
            dst[0] = __floats2half2_rn(tile[c4 + 0][l], tile[c4 + 1][l]);
            dst[1] = __floats2half2_rn(tile[c4 + 2][l], tile[c4 + 3][l]);
        }
        __syncthreads();
    }
}

// ============================================================================
// fp16 tensor-core GEMM: D[m,n] = sum_k A[m,k]*B[n,k]  (A:[M,K], B:[N,K] fp16)
// CTA: 128 thr (4 warps), 128x128 tile, warp tile 64x64 (2x2 warp grid).
// K-chunk 64 halves, 3-stage cp.async, XOR swizzle, ldmatrix fragment loads.
// EPI: 0 = fp16 out
//      4 = fp32 out + bias[m] + resid[m*ldc+n]
//      5 = merged QKV routing (q/k row-major + bias, v transposed + bias)
//      6 = scores: P = fp16(exp(c*alpha - EXP_SHIFT)), atomic row sums -> rsum
//      7 = PV: fp16 out scaled by 1/rsum[m]
// ============================================================================
#define STAGE_BYTES 32768   // A 16KB + B 16KB
#define GEMM_SMEM   (3 * STAGE_BYTES)

template<int EPI>
__global__ __launch_bounds__(128, 2)
void gemm_h(const __half* __restrict__ A, const __half* __restrict__ B,
            void* __restrict__ Dv, int K, int lda, int ldb, int ldc,
            long long sA, long long sB, long long sD,
            const float* __restrict__ bias, float alpha,
            const float* __restrict__ resid, float* __restrict__ rsum,
            void* __restrict__ Dv2, void* __restrict__ Dv3,
            const float* __restrict__ bias2, const float* __restrict__ bias3) {
    extern __shared__ char smem[];
    const uint32_t sb = (uint32_t)__cvta_generic_to_shared(smem);
    const int tid = threadIdx.x;
    const int lane = tid & 31;
    const int warp = tid >> 5;
    const int gid = lane >> 2;   // 0..7
    const int tig = lane & 3;    // 0..3
    const int wm = warp & 1;     // m half
    const int wn = warp >> 1;    // n half
    const int m0 = blockIdx.y * 128;
    const int n0 = blockIdx.x * 128;
    const int bz = blockIdx.z;

    A += (long long)bz * sA;
    B += (long long)bz * sB;

    // ---- cp.async loader geometry: rows lm + u*16, 16B granule lg
    const int lm = tid >> 3;          // 0..15
    const int lg = tid & 7;           // 0..7
    const __half* Ap = A + (long long)(m0 + lm) * lda + lg * 8;
    const __half* Bp = B + (long long)(n0 + lm) * ldb + lg * 8;
    const uint32_t sts_off = (uint32_t)(lm * 128 + (((lg ^ lm) & 7) << 4));

    // ---- ldmatrix geometry
    const int r7 = lane & 7;
    const int lhi = lane >> 4;
    const int arow = ((lane >> 3) & 1) * 8 + r7;
    const int bhi = (lane >> 3) & 1;
    const int brow = ((lane >> 4) & 1) * 8 + r7;
    uint32_t aRowOff[4], bRowOff[4];
#pragma unroll
    for (int mt = 0; mt < 4; mt++)
        aRowOff[mt] = (uint32_t)((wm * 64 + mt * 16 + arow) * 128);
#pragma unroll
    for (int j = 0; j < 4; j++)
        bRowOff[j] = (uint32_t)((wn * 64 + j * 16 + brow) * 128) + 16384u;

    const int nch = K / 64;

#define ISSUE_STAGE(st, buf) do {                                             \
        const uint32_t d0 = sb + (uint32_t)(buf) * STAGE_BYTES + sts_off;     \
        const __half* ap = Ap + (st) * 64;                                    \
        const __half* bp = Bp + (st) * 64;                                    \
        _Pragma("unroll")                                                     \
        for (int u = 0; u < 8; u++)                                           \
            cp_async16(d0 + u * 2048, ap + (long long)u * 16 * lda);          \
        _Pragma("unroll")                                                     \
        for (int u = 0; u < 8; u++)                                           \
            cp_async16(d0 + 16384 + u * 2048, bp + (long long)u * 16 * ldb);  \
    } while (0)

    ISSUE_STAGE(0, 0); cp_commit();
    ISSUE_STAGE(1, 1); cp_commit();

    float acc[4][8][4];
#pragma unroll
    for (int i = 0; i < 4; i++)
#pragma unroll
        for (int j = 0; j < 8; j++)
#pragma unroll
            for (int r = 0; r < 4; r++) acc[i][j][r] = 0.f;

    for (int i = 0; i < nch; i++) {
        cp_wait<1>();
        __syncthreads();
        if (i + 2 < nch) ISSUE_STAGE(i + 2, (i + 2) % 3);
        cp_commit();

        const uint32_t stage = sb + (uint32_t)(i % 3) * STAGE_BYTES;
#pragma unroll
        for (int ks = 0; ks < 4; ks++) {
            const uint32_t swa = (uint32_t)((((2 * ks + lhi) ^ r7) & 7) << 4);
            const uint32_t swb = (uint32_t)((((2 * ks + bhi) ^ r7) & 7) << 4);
            uint32_t afr[4][4], bfr[8][2];
#pragma unroll
            for (int mt = 0; mt < 4; mt++)
                ldsm_x4(afr[mt][0], afr[mt][1], afr[mt][2], afr[mt][3],
                        stage + aRowOff[mt] + swa);
#pragma unroll
            for (int j = 0; j < 4; j++)
                ldsm_x4(bfr[2 * j][0], bfr[2 * j][1], bfr[2 * j + 1][0],
                        bfr[2 * j + 1][1], stage + bRowOff[j] + swb);
#pragma unroll
            for (int mt = 0; mt < 4; mt++)
#pragma unroll
                for (int nt = 0; nt < 8; nt++)
                    mma_f16(acc[mt][nt], afr[mt], bfr[nt]);
        }
    }
#undef ISSUE_STAGE

    // epilogue
#pragma unroll
    for (int mt = 0; mt < 4; mt++) {
        const int m = m0 + wm * 64 + mt * 16 + gid;
        float rs0 = 0.f, rs1 = 0.f;            // EPI 6 row-sum partials
        float inv0 = 1.f, inv1 = 1.f;          // EPI 7 row scales
        if (EPI == 7) {
            inv0 = 1.f / rsum[(long long)bz * LDIM + m];
            inv1 = 1.f / rsum[(long long)bz * LDIM + m + 8];
        }
#pragma unroll
        for (int nt = 0; nt < 8; nt++) {
            const int n = n0 + wn * 64 + nt * 8 + tig * 2;
            float* c = acc[mt][nt];
            if (EPI == 0) {
                __half* Dh = (__half*)Dv + (long long)bz * sD;
                *reinterpret_cast<__half2*>(Dh + (long long)m * ldc + n) =
                    __floats2half2_rn(c[0], c[1]);
                *reinterpret_cast<__half2*>(Dh + (long long)(m + 8) * ldc + n) =
                    __floats2half2_rn(c[2], c[3]);
            } else if (EPI == 4) {
                float* Df = (float*)Dv + (long long)bz * sD;
                const float* rs = resid + (long long)bz * sD;
                const float bm0 = bias[m], bm1 = bias[m + 8];
                const float2 r0 = *reinterpret_cast<const float2*>(
                    &rs[(long long)m * ldc + n]);
                const float2 r1 = *reinterpret_cast<const float2*>(
                    &rs[(long long)(m + 8) * ldc + n]);
                *reinterpret_cast<float2*>(&Df[(long long)m * ldc + n]) =
                    make_float2(c[0] + bm0 + r0.x, c[1] + bm0 + r0.y);
                *reinterpret_cast<float2*>(&Df[(long long)(m + 8) * ldc + n]) =
                    make_float2(c[2] + bm1 + r1.x, c[3] + bm1 + r1.y);
            } else if (EPI == 5) {  // merged QKV routing
                const int which = n >> 9;          // 0=q, 1=k, 2=v
                const int nl = n & 511;
                if (which < 2) {
                    __half* Dh = ((which == 0) ? (__half*)Dv : (__half*)Dv2)
                                 + (long long)bz * CL;
                    const float* bb = (which == 0) ? bias : bias2;
                    const float b0v = bb[nl], b1v = bb[nl + 1];
                    *reinterpret_cast<__half2*>(Dh + (long long)m * CDIM + nl) =
                        __floats2half2_rn(c[0] + b0v, c[1] + b1v);
                    *reinterpret_cast<__half2*>(Dh + (long long)(m + 8) * CDIM + nl) =
                        __floats2half2_rn(c[2] + b0v, c[3] + b1v);
                } else {
                    __half* Dh = (__half*)Dv3 + (long long)bz * CL;
                    const float b0v = bias3[nl], b1v = bias3[nl + 1];
                    Dh[(long long)nl * LDIM + m]           = __float2half(c[0] + b0v);
                    Dh[(long long)(nl + 1) * LDIM + m]     = __float2half(c[1] + b1v);
                    Dh[(long long)nl * LDIM + m + 8]       = __float2half(c[2] + b0v);
                    Dh[(long long)(nl + 1) * LDIM + m + 8] = __float2half(c[3] + b1v);
                }
            } else if (EPI == 6) {  // scores -> unnormalized softmax numerator
                __half* Dh = (__half*)Dv + (long long)bz * sD;
                const float e0 = __expf(c[0] * alpha - EXP_SHIFT);
                const float e1 = __expf(c[1] * alpha - EXP_SHIFT);
                const float e2 = __expf(c[2] * alpha - EXP_SHIFT);
                const float e3 = __expf(c[3] * alpha - EXP_SHIFT);
                *reinterpret_cast<__half2*>(Dh + (long long)m * ldc + n) =
                    __floats2half2_rn(e0, e1);
                *reinterpret_cast<__half2*>(Dh + (long long)(m + 8) * ldc + n) =
                    __floats2half2_rn(e2, e3);
                rs0 += e0 + e1;
                rs1 += e2 + e3;
            } else {  // EPI == 7: PV with row normalization
                __half* Dh = (__half*)Dv + (long long)bz * sD;
                *reinterpret_cast<__half2*>(Dh + (long long)m * ldc + n) =
                    __floats2half2_rn(c[0] * inv0, c[1] * inv0);
                *reinterpret_cast<__half2*>(Dh + (long long)(m + 8) * ldc + n) =
                    __floats2half2_rn(c[2] * inv1, c[3] * inv1);
            }
        }
        if (EPI == 6) {
            // reduce across the 4 lanes of the quad (tig bits = lane bits 0,1)
            rs0 += __shfl_xor_sync(0xFFFFFFFFu, rs0, 1);
            rs0 += __shfl_xor_sync(0xFFFFFFFFu, rs0, 2);
            rs1 += __shfl_xor_sync(0xFFFFFFFFu, rs1, 1);
            rs1 += __shfl_xor_sync(0xFFFFFFFFu, rs1, 2);
            if (tig == 0) {
                atomicAdd(&rsum[(long long)bz * LDIM + m], rs0);
                atomicAdd(&rsum[(long long)bz * LDIM + m + 8], rs1);
            }
        }
    }
}

// ============================================================================
// Launch
// ============================================================================
extern "C" void kernel_launch(void* const* d_in, const int* in_sizes, int n_in,
                              void* d_out, int out_size) {
    (void)in_sizes; (void)n_in; (void)out_size;
    const float* x   = (const float*)d_in[0];
    const float* gns = (const float*)d_in[1];
    const float* gnb = (const float*)d_in[2];
    const float* wq  = (const float*)d_in[3];
    const float* bq  = (const float*)d_in[4];
    const float* wk  = (const float*)d_in[5];
    const float* bk  = (const float*)d_in[6];
    const float* wv  = (const float*)d_in[7];
    const float* bv  = (const float*)d_in[8];
    const float* wo  = (const float*)d_in[9];
    const float* bo  = (const float*)d_in[10];
    float* out = (float*)d_out;

    unsigned char* base = nullptr;
    cudaGetSymbolAddress((void**)&base, g_scratch);
    __half* ht   = (__half*)(base);
    __half* qh   = (__half*)(base + 16777216);
    __half* kh   = (__half*)(base + 33554432);
    __half* vTh  = (__half*)(base + 50331648);
    __half* ah   = (__half*)(base + 67108864);
    float*  rsum = (float*)(base + 83886080);
    __half* p    = (__half*)(base + 218103808);
    __half* wh   = (__half*)(base + 285212672);   // [wq|wk|wv] stacked, then wo
    __half* woh  = wh + 786432;

    const float attn_scale = 0.044194173824159216f;  // 512^-0.5

    static bool attr_done = false;
    if (!attr_done) {
        cudaFuncSetAttribute(gemm_h<4>, cudaFuncAttributeMaxDynamicSharedMemorySize, GEMM_SMEM);
        cudaFuncSetAttribute(gemm_h<5>, cudaFuncAttributeMaxDynamicSharedMemorySize, GEMM_SMEM);
        cudaFuncSetAttribute(gemm_h<6>, cudaFuncAttributeMaxDynamicSharedMemorySize, GEMM_SMEM);
        cudaFuncSetAttribute(gemm_h<7>, cudaFuncAttributeMaxDynamicSharedMemorySize, GEMM_SMEM);
        attr_done = true;
    }

    // 0) Weights -> fp16 + zero rsum
    conv_w_kernel<<<4096, 256>>>(wq, wk, wv, wo, wh, rsum);

    // 1) GroupNorm + transpose: ht [B, L, C] fp16
    gn_t_kernel<<<BDIM * NGRP, 256>>>(x, gns, gnb, ht);

    // 2) Merged QKV projection: M=L, N=3C=1536, K=C; routed epilogue
    {
        dim3 grid(1536 / 128, LDIM / 128, BDIM);
        gemm_h<5><<<grid, 128, GEMM_SMEM>>>(ht, wh, qh, CDIM, CDIM, CDIM, CDIM,
            CL, 0, CL, bq, 0.f, nullptr, nullptr, kh, vTh, bk, bv);
    }

    // 3) Scores fused with exp: p[i,j] = fp16(exp(scale*q.k - 4)), rsum[i] += ...
    {
        dim3 grid(LDIM / 128, LDIM / 128, BDIM);
        gemm_h<6><<<grid, 128, GEMM_SMEM>>>(qh, kh, p, CDIM, CDIM, CDIM, LDIM,
            CL, CL, LL, nullptr, attn_scale, nullptr, rsum, nullptr, nullptr,
            nullptr, nullptr);
    }

    // 4) PV with normalization: a[i,c] = (sum_j p[i,j] * vT[c,j]) / rsum[i]
    {
        dim3 grid(CDIM / 128, LDIM / 128, BDIM);
        gemm_h<7><<<grid, 128, GEMM_SMEM>>>(p, vTh, ah, LDIM, LDIM, LDIM, CDIM,
            LL, CL, CL, nullptr, 0.f, nullptr, rsum, nullptr, nullptr,
            nullptr, nullptr);
    }

    // 5) out[o,l] = sum_c wo[o,c] * a[l,c] + bo[o] + x[o,l]  (M=C, N=L, fp32 out)
    {
        dim3 grid(LDIM / 128, CDIM / 128, BDIM);
        gemm_h<4><<<grid, 128, GEMM_SMEM>>>(woh, ah, out, CDIM, CDIM, CDIM, LDIM,
            0, CL, CL, bo, 0.f, x, nullptr, nullptr, nullptr, nullptr, nullptr);
    }
}

// round 10
// speedup vs baseline: 8.4380x; 1.0015x over previous
#include <cuda_runtime.h>
#include <cuda_fp16.h>
#include <cstdint>

// Problem: x [B=8, C=512, L=2048], GroupNorm(32) -> QKV -> attention -> O-proj + residual.
#define BDIM 8
#define CDIM 512
#define LDIM 2048
#define NGRP 32
#define CPG  (CDIM / NGRP)   // 16
#define GN_EPS 1e-5f
#define EXP_SHIFT 4.0f

#define CL 1048576LL   // C*L per-batch elems
#define LL 4194304LL   // L*L per-batch elems

// Scratch (bytes):
//  ht  [B,L,C] fp16 @ 0
//  qh  [B,L,C] fp16 @ 16777216
//  kh  [B,L,C] fp16 @ 33554432
//  vTh [B,C,L] fp16 @ 50331648
//  ah  [B,L,C] fp16 @ 67108864
//  rsum [B,L] fp32 @ 83886080   (65,536)
//  p   [B,L,L] fp16 @ 218103808 (67,108,864)
//  wh  4x[C,C] fp16 @ 285212672 (wq|wk|wv stacked = [3C,C], then wo)
__device__ __align__(256) unsigned char g_scratch[287309824];

// ---------------------------------------------------------------------------
__device__ __forceinline__ float warp_sum(float v) {
#pragma unroll
    for (int o = 16; o > 0; o >>= 1) v += __shfl_xor_sync(0xFFFFFFFFu, v, o);
    return v;
}
// fp16 MMA, fp32 accumulate: D[16x8] += A[16x16] * B[16x8]
__device__ __forceinline__ void mma_f16(float* c, const uint32_t* a, const uint32_t* b) {
    asm volatile(
        "mma.sync.aligned.m16n8k16.row.col.f32.f16.f16.f32 "
        "{%0,%1,%2,%3}, {%4,%5,%6,%7}, {%8,%9}, {%0,%1,%2,%3};"
        : "+f"(c[0]), "+f"(c[1]), "+f"(c[2]), "+f"(c[3])
        : "r"(a[0]), "r"(a[1]), "r"(a[2]), "r"(a[3]), "r"(b[0]), "r"(b[1]));
}
__device__ __forceinline__ void ldsm_x4(uint32_t& r0, uint32_t& r1, uint32_t& r2,
                                        uint32_t& r3, uint32_t addr) {
    asm volatile("ldmatrix.sync.aligned.m8n8.x4.shared.b16 {%0,%1,%2,%3}, [%4];"
                 : "=r"(r0), "=r"(r1), "=r"(r2), "=r"(r3) : "r"(addr));
}
__device__ __forceinline__ void cp_async16(uint32_t dst, const void* src) {
    asm volatile("cp.async.cg.shared.global [%0], [%1], 16;" :: "r"(dst), "l"(src));
}
__device__ __forceinline__ void cp_commit() {
    asm volatile("cp.async.commit_group;" ::: "memory");
}
template<int N>
__device__ __forceinline__ void cp_wait() {
    asm volatile("cp.async.wait_group %0;" :: "n"(N) : "memory");
}

// ============================================================================
// Weight convert + rsum zero
// ============================================================================
__global__ __launch_bounds__(256)
void conv_w_kernel(const float* __restrict__ wq, const float* __restrict__ wk,
                   const float* __restrict__ wv, const float* __restrict__ wo,
                   __half* __restrict__ dst, float* __restrict__ rsum) {
    int i = blockIdx.x * 256 + threadIdx.x;
    int which = i >> 18;
    int off = i & 0x3FFFF;
    const float* src = (which == 0) ? wq : (which == 1) ? wk : (which == 2) ? wv : wo;
    dst[i] = __float2half(src[off]);
    if (i < BDIM * LDIM) rsum[i] = 0.f;
}

// ============================================================================
// GroupNorm fused with transpose: x [B,C,L] fp32 -> ht [B,L,C] fp16
// ============================================================================
__global__ __launch_bounds__(256)
void gn_t_kernel(const float* __restrict__ x, const float* __restrict__ gamma,
                 const float* __restrict__ beta, __half* __restrict__ ht) {
    const int b = blockIdx.x / NGRP;
    const int g = blockIdx.x % NGRP;
    const size_t base = ((size_t)b * CDIM + (size_t)g * CPG) * LDIM;
    const float4* xp = reinterpret_cast<const float4*>(x + base);

    const int n4 = CPG * LDIM / 4;  // 8192
    float s = 0.f, ss = 0.f;
    for (int i = threadIdx.x; i < n4; i += 256) {
        float4 t = xp[i];
        s  += t.x + t.y + t.z + t.w;
        ss += t.x * t.x + t.y * t.y + t.z * t.z + t.w * t.w;
    }
    __shared__ float sh1[8], sh2[8];
    __shared__ float scg[CPG], sbg[CPG];
    int lane = threadIdx.x & 31, wid = threadIdx.x >> 5;
    s = warp_sum(s); ss = warp_sum(ss);
    if (lane == 0) { sh1[wid] = s; sh2[wid] = ss; }
    __syncthreads();
    if (wid == 0) {
        s  = (lane < 8) ? sh1[lane] : 0.f;
        ss = (lane < 8) ? sh2[lane] : 0.f;
        s = warp_sum(s); ss = warp_sum(ss);
        if (lane == 0) { sh1[0] = s; sh2[0] = ss; }
    }
    __syncthreads();
    const float inv_n = 1.f / (float)(CPG * LDIM);
    const float mean = sh1[0] * inv_n;
    const float var  = sh2[0] * inv_n - mean * mean;
    const float rstd = rsqrtf(var + GN_EPS);
    if (threadIdx.x < CPG) {
        float sc = gamma[g * CPG + threadIdx.x] * rstd;
        scg[threadIdx.x] = sc;
        sbg[threadIdx.x] = beta[g * CPG + threadIdx.x] - mean * sc;
    }
    __syncthreads();

    __shared__ float tile[CPG][133];
    for (int l0 = 0; l0 < LDIM; l0 += 128) {
        for (int it = threadIdx.x; it < 512; it += 256) {
            int c  = it >> 5;
            int l4 = (it & 31) * 4;
            float4 t = *reinterpret_cast<const float4*>(&x[base + (size_t)c * LDIM + l0 + l4]);
            float sc = scg[c], sb = sbg[c];
            tile[c][l4 + 0] = t.x * sc + sb;
            tile[c][l4 + 1] = t.y * sc + sb;
            tile[c][l4 + 2] = t.z * sc + sb;
            tile[c][l4 + 3] = t.w * sc + sb;
        }
        __syncthreads();
        for (int it = threadIdx.x; it < 512; it += 256) {
            int l  = it >> 2;
            int c4 = (it & 3) * 4;
            __half2* dst = reinterpret_cast<__half2*>(
                ht + ((size_t)b * LDIM + l0 + l) * CDIM + g * CPG + c4);
            dst[0] = __floats2half2_rn(tile[c4 + 0][l], tile[c4 + 1][l]);
            dst[1] = __floats2half2_rn(tile[c4 + 2][l], tile[c4 + 3][l]);
        }
        __syncthreads();
    }
}

// ============================================================================
// fp16 tensor-core GEMM: D[m,n] = sum_k A[m,k]*B[n,k]  (A:[M,K], B:[N,K] fp16)
// CTA: 128 thr (4 warps), 128x128 tile, warp tile 64x64 (2x2 warp grid).
// K-chunk 64 halves, 3-stage cp.async, XOR swizzle, ldmatrix fragment loads,
// register double-buffered fragments (LDSM for ks+1 issued under MMAs of ks).
// EPI: 0 = fp16 out
//      4 = fp32 out + bias[m] + resid[m*ldc+n]
//      5 = merged QKV routing (q/k row-major + bias, v transposed + bias)
//      6 = scores: P = fp16(exp(c*alpha - EXP_SHIFT)), atomic row sums -> rsum
//      7 = PV: fp16 out scaled by 1/rsum[m]
// ============================================================================
#define STAGE_BYTES 32768   // A 16KB + B 16KB
#define GEMM_SMEM   (3 * STAGE_BYTES)

template<int EPI>
__global__ __launch_bounds__(128, 2)
void gemm_h(const __half* __restrict__ A, const __half* __restrict__ B,
            void* __restrict__ Dv, int K, int lda, int ldb, int ldc,
            long long sA, long long sB, long long sD,
            const float* __restrict__ bias, float alpha,
            const float* __restrict__ resid, float* __restrict__ rsum,
            void* __restrict__ Dv2, void* __restrict__ Dv3,
            const float* __restrict__ bias2, const float* __restrict__ bias3) {
    extern __shared__ char smem[];
    const uint32_t sb = (uint32_t)__cvta_generic_to_shared(smem);
    const int tid = threadIdx.x;
    const int lane = tid & 31;
    const int warp = tid >> 5;
    const int gid = lane >> 2;   // 0..7
    const int tig = lane & 3;    // 0..3
    const int wm = warp & 1;     // m half
    const int wn = warp >> 1;    // n half
    const int m0 = blockIdx.y * 128;
    const int n0 = blockIdx.x * 128;
    const int bz = blockIdx.z;

    A += (long long)bz * sA;
    B += (long long)bz * sB;

    // ---- cp.async loader geometry: rows lm + u*16, 16B granule lg
    const int lm = tid >> 3;          // 0..15
    const int lg = tid & 7;           // 0..7
    const __half* Ap = A + (long long)(m0 + lm) * lda + lg * 8;
    const __half* Bp = B + (long long)(n0 + lm) * ldb + lg * 8;
    const uint32_t sts_off = (uint32_t)(lm * 128 + (((lg ^ lm) & 7) << 4));

    // ---- ldmatrix geometry
    const int r7 = lane & 7;
    const int lhi = lane >> 4;
    const int arow = ((lane >> 3) & 1) * 8 + r7;
    const int bhi = (lane >> 3) & 1;
    const int brow = ((lane >> 4) & 1) * 8 + r7;
    uint32_t aRowOff[4], bRowOff[4];
#pragma unroll
    for (int mt = 0; mt < 4; mt++)
        aRowOff[mt] = (uint32_t)((wm * 64 + mt * 16 + arow) * 128);
#pragma unroll
    for (int j = 0; j < 4; j++)
        bRowOff[j] = (uint32_t)((wn * 64 + j * 16 + brow) * 128) + 16384u;

    const int nch = K / 64;

#define ISSUE_STAGE(st, buf) do {                                             \
        const uint32_t d0 = sb + (uint32_t)(buf) * STAGE_BYTES + sts_off;     \
        const __half* ap = Ap + (st) * 64;                                    \
        const __half* bp = Bp + (st) * 64;                                    \
        _Pragma("unroll")                                                     \
        for (int u = 0; u < 8; u++)                                           \
            cp_async16(d0 + u * 2048, ap + (long long)u * 16 * lda);          \
        _Pragma("unroll")                                                     \
        for (int u = 0; u < 8; u++)                                           \
            cp_async16(d0 + 16384 + u * 2048, bp + (long long)u * 16 * ldb);  \
    } while (0)

// load one k-step's fragments into register buffer slot `sl`
#define LOAD_FRAGS(sl, ks_) do {                                              \
        const uint32_t swa = (uint32_t)((((2 * (ks_) + lhi) ^ r7) & 7) << 4); \
        const uint32_t swb = (uint32_t)((((2 * (ks_) + bhi) ^ r7) & 7) << 4); \
        _Pragma("unroll")                                                     \
        for (int mt = 0; mt < 4; mt++)                                        \
            ldsm_x4(afr[sl][mt][0], afr[sl][mt][1], afr[sl][mt][2],           \
                    afr[sl][mt][3], stage + aRowOff[mt] + swa);               \
        _Pragma("unroll")                                                     \
        for (int j = 0; j < 4; j++)                                           \
            ldsm_x4(bfr[sl][2 * j][0], bfr[sl][2 * j][1],                     \
                    bfr[sl][2 * j + 1][0], bfr[sl][2 * j + 1][1],             \
                    stage + bRowOff[j] + swb);                                \
    } while (0)

    ISSUE_STAGE(0, 0); cp_commit();
    ISSUE_STAGE(1, 1); cp_commit();

    float acc[4][8][4];
#pragma unroll
    for (int i = 0; i < 4; i++)
#pragma unroll
        for (int j = 0; j < 8; j++)
#pragma unroll
            for (int r = 0; r < 4; r++) acc[i][j][r] = 0.f;

    uint32_t afr[2][4][4], bfr[2][8][2];

    for (int i = 0; i < nch; i++) {
        cp_wait<1>();
        __syncthreads();
        if (i + 2 < nch) ISSUE_STAGE(i + 2, (i + 2) % 3);
        cp_commit();

        const uint32_t stage = sb + (uint32_t)(i % 3) * STAGE_BYTES;
        LOAD_FRAGS(0, 0);
#pragma unroll
        for (int ks = 0; ks < 4; ks++) {
            if (ks < 3) LOAD_FRAGS((ks + 1) & 1, ks + 1);
            const int cur = ks & 1;
#pragma unroll
            for (int mt = 0; mt < 4; mt++)
#pragma unroll
                for (int nt = 0; nt < 8; nt++)
                    mma_f16(acc[mt][nt], afr[cur][mt], bfr[cur][nt]);
        }
    }
#undef ISSUE_STAGE
#undef LOAD_FRAGS

    // epilogue
#pragma unroll
    for (int mt = 0; mt < 4; mt++) {
        const int m = m0 + wm * 64 + mt * 16 + gid;
        float rs0 = 0.f, rs1 = 0.f;            // EPI 6 row-sum partials
        float inv0 = 1.f, inv1 = 1.f;          // EPI 7 row scales
        if (EPI == 7) {
            inv0 = 1.f / rsum[(long long)bz * LDIM + m];
            inv1 = 1.f / rsum[(long long)bz * LDIM + m + 8];
        }
#pragma unroll
        for (int nt = 0; nt < 8; nt++) {
            const int n = n0 + wn * 64 + nt * 8 + tig * 2;
            float* c = acc[mt][nt];
            if (EPI == 0) {
                __half* Dh = (__half*)Dv + (long long)bz * sD;
                *reinterpret_cast<__half2*>(Dh + (long long)m * ldc + n) =
                    __floats2half2_rn(c[0], c[1]);
                *reinterpret_cast<__half2*>(Dh + (long long)(m + 8) * ldc + n) =
                    __floats2half2_rn(c[2], c[3]);
            } else if (EPI == 4) {
                float* Df = (float*)Dv + (long long)bz * sD;
                const float* rs = resid + (long long)bz * sD;
                const float bm0 = bias[m], bm1 = bias[m + 8];
                const float2 r0 = *reinterpret_cast<const float2*>(
                    &rs[(long long)m * ldc + n]);
                const float2 r1 = *reinterpret_cast<const float2*>(
                    &rs[(long long)(m + 8) * ldc + n]);
                *reinterpret_cast<float2*>(&Df[(long long)m * ldc + n]) =
                    make_float2(c[0] + bm0 + r0.x, c[1] + bm0 + r0.y);
                *reinterpret_cast<float2*>(&Df[(long long)(m + 8) * ldc + n]) =
                    make_float2(c[2] + bm1 + r1.x, c[3] + bm1 + r1.y);
            } else if (EPI == 5) {  // merged QKV routing
                const int which = n >> 9;          // 0=q, 1=k, 2=v
                const int nl = n & 511;
                if (which < 2) {
                    __half* Dh = ((which == 0) ? (__half*)Dv : (__half*)Dv2)
                                 + (long long)bz * CL;
                    const float* bb = (which == 0) ? bias : bias2;
                    const float b0v = bb[nl], b1v = bb[nl + 1];
                    *reinterpret_cast<__half2*>(Dh + (long long)m * CDIM + nl) =
                        __floats2half2_rn(c[0] + b0v, c[1] + b1v);
                    *reinterpret_cast<__half2*>(Dh + (long long)(m + 8) * CDIM + nl) =
                        __floats2half2_rn(c[2] + b0v, c[3] + b1v);
                } else {
                    __half* Dh = (__half*)Dv3 + (long long)bz * CL;
                    const float b0v = bias3[nl], b1v = bias3[nl + 1];
                    Dh[(long long)nl * LDIM + m]           = __float2half(c[0] + b0v);
                    Dh[(long long)(nl + 1) * LDIM + m]     = __float2half(c[1] + b1v);
                    Dh[(long long)nl * LDIM + m + 8]       = __float2half(c[2] + b0v);
                    Dh[(long long)(nl + 1) * LDIM + m + 8] = __float2half(c[3] + b1v);
                }
            } else if (EPI == 6) {  // scores -> unnormalized softmax numerator
                __half* Dh = (__half*)Dv + (long long)bz * sD;
                const float e0 = __expf(c[0] * alpha - EXP_SHIFT);
                const float e1 = __expf(c[1] * alpha - EXP_SHIFT);
                const float e2 = __expf(c[2] * alpha - EXP_SHIFT);
                const float e3 = __expf(c[3] * alpha - EXP_SHIFT);
                *reinterpret_cast<__half2*>(Dh + (long long)m * ldc + n) =
                    __floats2half2_rn(e0, e1);
                *reinterpret_cast<__half2*>(Dh + (long long)(m + 8) * ldc + n) =
                    __floats2half2_rn(e2, e3);
                rs0 += e0 + e1;
                rs1 += e2 + e3;
            } else {  // EPI == 7: PV with row normalization
                __half* Dh = (__half*)Dv + (long long)bz * sD;
                *reinterpret_cast<__half2*>(Dh + (long long)m * ldc + n) =
                    __floats2half2_rn(c[0] * inv0, c[1] * inv0);
                *reinterpret_cast<__half2*>(Dh + (long long)(m + 8) * ldc + n) =
                    __floats2half2_rn(c[2] * inv1, c[3] * inv1);
            }
        }
        if (EPI == 6) {
            rs0 += __shfl_xor_sync(0xFFFFFFFFu, rs0, 1);
            rs0 += __shfl_xor_sync(0xFFFFFFFFu, rs0, 2);
            rs1 += __shfl_xor_sync(0xFFFFFFFFu, rs1, 1);
            rs1 += __shfl_xor_sync(0xFFFFFFFFu, rs1, 2);
            if (tig == 0) {
                atomicAdd(&rsum[(long long)bz * LDIM + m], rs0);
                atomicAdd(&rsum[(long long)bz * LDIM + m + 8], rs1);
            }
        }
    }
}

// ============================================================================
// Launch
// ============================================================================
extern "C" void kernel_launch(void* const* d_in, const int* in_sizes, int n_in,
                              void* d_out, int out_size) {
    (void)in_sizes; (void)n_in; (void)out_size;
    const float* x   = (const float*)d_in[0];
    const float* gns = (const float*)d_in[1];
    const float* gnb = (const float*)d_in[2];
    const float* wq  = (const float*)d_in[3];
    const float* bq  = (const float*)d_in[4];
    const float* wk  = (const float*)d_in[5];
    const float* bk  = (const float*)d_in[6];
    const float* wv  = (const float*)d_in[7];
    const float* bv  = (const float*)d_in[8];
    const float* wo  = (const float*)d_in[9];
    const float* bo  = (const float*)d_in[10];
    float* out = (float*)d_out;

    unsigned char* base = nullptr;
    cudaGetSymbolAddress((void**)&base, g_scratch);
    __half* ht   = (__half*)(base);
    __half* qh   = (__half*)(base + 16777216);
    __half* kh   = (__half*)(base + 33554432);
    __half* vTh  = (__half*)(base + 50331648);
    __half* ah   = (__half*)(base + 67108864);
    float*  rsum = (float*)(base + 83886080);
    __half* p    = (__half*)(base + 218103808);
    __half* wh   = (__half*)(base + 285212672);   // [wq|wk|wv] stacked, then wo
    __half* woh  = wh + 786432;

    const float attn_scale = 0.044194173824159216f;  // 512^-0.5

    static bool attr_done = false;
    if (!attr_done) {
        cudaFuncSetAttribute(gemm_h<4>, cudaFuncAttributeMaxDynamicSharedMemorySize, GEMM_SMEM);
        cudaFuncSetAttribute(gemm_h<5>, cudaFuncAttributeMaxDynamicSharedMemorySize, GEMM_SMEM);
        cudaFuncSetAttribute(gemm_h<6>, cudaFuncAttributeMaxDynamicSharedMemorySize, GEMM_SMEM);
        cudaFuncSetAttribute(gemm_h<7>, cudaFuncAttributeMaxDynamicSharedMemorySize, GEMM_SMEM);
        attr_done = true;
    }

    // 0) Weights -> fp16 + zero rsum
    conv_w_kernel<<<4096, 256>>>(wq, wk, wv, wo, wh, rsum);

    // 1) GroupNorm + transpose: ht [B, L, C] fp16
    gn_t_kernel<<<BDIM * NGRP, 256>>>(x, gns, gnb, ht);

    // 2) Merged QKV projection: M=L, N=3C=1536, K=C; routed epilogue
    {
        dim3 grid(1536 / 128, LDIM / 128, BDIM);
        gemm_h<5><<<grid, 128, GEMM_SMEM>>>(ht, wh, qh, CDIM, CDIM, CDIM, CDIM,
            CL, 0, CL, bq, 0.f, nullptr, nullptr, kh, vTh, bk, bv);
    }

    // 3) Scores fused with exp: p[i,j] = fp16(exp(scale*q.k - 4)), rsum[i] += ...
    {
        dim3 grid(LDIM / 128, LDIM / 128, BDIM);
        gemm_h<6><<<grid, 128, GEMM_SMEM>>>(qh, kh, p, CDIM, CDIM, CDIM, LDIM,
            CL, CL, LL, nullptr, attn_scale, nullptr, rsum, nullptr, nullptr,
            nullptr, nullptr);
    }

    // 4) PV with normalization: a[i,c] = (sum_j p[i,j] * vT[c,j]) / rsum[i]
    {
        dim3 grid(CDIM / 128, LDIM / 128, BDIM);
        gemm_h<7><<<grid, 128, GEMM_SMEM>>>(p, vTh, ah, LDIM, LDIM, LDIM, CDIM,
            LL, CL, CL, nullptr, 0.f, nullptr, rsum, nullptr, nullptr,
            nullptr, nullptr);
    }

    // 5) out[o,l] = sum_c wo[o,c] * a[l,c] + bo[o] + x[o,l]  (M=C, N=L, fp32 out)
    {
        dim3 grid(LDIM / 128, CDIM / 128, BDIM);
        gemm_h<4><<<grid, 128, GEMM_SMEM>>>(woh, ah, out, CDIM, CDIM, CDIM, LDIM,
            0, CL, CL, bo, 0.f, x, nullptr, nullptr, nullptr, nullptr, nullptr);
    }
}

// round 11
// speedup vs baseline: 8.6884x; 1.0297x over previous
#include <cuda_runtime.h>
#include <cuda_fp16.h>
#include <cstdint>

// Problem: x [B=8, C=512, L=2048], GroupNorm(32) -> QKV -> attention -> O-proj + residual.
// Algebra: out = Pn @ (h @ (Wo·Wv)^T) + (Wo·bv + bo) + x   (softmax rows sum to 1)
#define BDIM 8
#define CDIM 512
#define LDIM 2048
#define NGRP 32
#define CPG  (CDIM / NGRP)   // 16
#define GN_EPS 1e-5f
#define EXP_SHIFT 4.0f

#define CL 1048576LL   // C*L per-batch elems
#define LL 4194304LL   // L*L per-batch elems

// Scratch (bytes):
//  ht   [B,L,C] fp16 @ 0
//  qh   [B,L,C] fp16 @ 16777216
//  kh   [B,L,C] fp16 @ 33554432
//  uTh  [B,C,L] fp16 @ 50331648      (u transposed)
//  rsum [B,L]  fp32 @ 67108864       (65,536)
//  b2   [C]    fp32 @ 67174400       (2,048)
//  p    [B,L,L] fp16 @ 83886080      (67,108,864)
//  wh   [3C,C] fp16 @ 150994944      (wq | wk | W2) 1,572,864
//  wvT  [C,C]  fp16 @ 152567808      (524,288)
//  wo_h [C,C]  fp16 @ 153092096      (524,288)
__device__ __align__(256) unsigned char g_scratch[153616384];

// ---------------------------------------------------------------------------
__device__ __forceinline__ float warp_sum(float v) {
#pragma unroll
    for (int o = 16; o > 0; o >>= 1) v += __shfl_xor_sync(0xFFFFFFFFu, v, o);
    return v;
}
// fp16 MMA, fp32 accumulate: D[16x8] += A[16x16] * B[16x8]
__device__ __forceinline__ void mma_f16(float* c, const uint32_t* a, const uint32_t* b) {
    asm volatile(
        "mma.sync.aligned.m16n8k16.row.col.f32.f16.f16.f32 "
        "{%0,%1,%2,%3}, {%4,%5,%6,%7}, {%8,%9}, {%0,%1,%2,%3};"
        : "+f"(c[0]), "+f"(c[1]), "+f"(c[2]), "+f"(c[3])
        : "r"(a[0]), "r"(a[1]), "r"(a[2]), "r"(a[3]), "r"(b[0]), "r"(b[1]));
}
__device__ __forceinline__ void ldsm_x4(uint32_t& r0, uint32_t& r1, uint32_t& r2,
                                        uint32_t& r3, uint32_t addr) {
    asm volatile("ldmatrix.sync.aligned.m8n8.x4.shared.b16 {%0,%1,%2,%3}, [%4];"
                 : "=r"(r0), "=r"(r1), "=r"(r2), "=r"(r3) : "r"(addr));
}
__device__ __forceinline__ void cp_async16(uint32_t dst, const void* src) {
    asm volatile("cp.async.cg.shared.global [%0], [%1], 16;" :: "r"(dst), "l"(src));
}
__device__ __forceinline__ void cp_commit() {
    asm volatile("cp.async.commit_group;" ::: "memory");
}
template<int N>
__device__ __forceinline__ void cp_wait() {
    asm volatile("cp.async.wait_group %0;" :: "n"(N) : "memory");
}

// ============================================================================
// Weight convert: wq->wh0, wk->wh1, wv->wvT (transposed), wo->wo_h; zero rsum
// ============================================================================
__global__ __launch_bounds__(256)
void conv_w_kernel(const float* __restrict__ wq, const float* __restrict__ wk,
                   const float* __restrict__ wv, const float* __restrict__ wo,
                   __half* __restrict__ wh, __half* __restrict__ wvT,
                   __half* __restrict__ wo_h, float* __restrict__ rsum) {
    int i = blockIdx.x * 256 + threadIdx.x;        // 0 .. 4*262144-1
    int which = i >> 18;
    int off = i & 0x3FFFF;
    if (which == 0) {
        wh[off] = __float2half(wq[off]);
    } else if (which == 1) {
        wh[262144 + off] = __float2half(wk[off]);
    } else if (which == 2) {
        // wv[c, e] -> wvT[e, c]
        int c = off >> 9, e = off & 511;
        wvT[e * 512 + c] = __float2half(wv[off]);
    } else {
        wo_h[off] = __float2half(wo[off]);
    }
    if (i < BDIM * LDIM) rsum[i] = 0.f;
}

// ============================================================================
// b2[o] = sum_c wo[o,c] * bv[c] + bo[o]   (fp32, one warp per o)
// ============================================================================
__global__ __launch_bounds__(256)
void bias2_kernel(const float* __restrict__ wo, const float* __restrict__ bv,
                  const float* __restrict__ bo, float* __restrict__ b2) {
    const int o = blockIdx.x * 8 + (threadIdx.x >> 5);   // 64 blocks x 8 warps
    const int lane = threadIdx.x & 31;
    float s = 0.f;
    for (int c = lane; c < CDIM; c += 32) s += wo[o * CDIM + c] * bv[c];
    s = warp_sum(s);
    if (lane == 0) b2[o] = s + bo[o];
}

// ============================================================================
// GroupNorm fused with transpose: x [B,C,L] fp32 -> ht [B,L,C] fp16
// ============================================================================
__global__ __launch_bounds__(256)
void gn_t_kernel(const float* __restrict__ x, const float* __restrict__ gamma,
                 const float* __restrict__ beta, __half* __restrict__ ht) {
    const int b = blockIdx.x / NGRP;
    const int g = blockIdx.x % NGRP;
    const size_t base = ((size_t)b * CDIM + (size_t)g * CPG) * LDIM;
    const float4* xp = reinterpret_cast<const float4*>(x + base);

    const int n4 = CPG * LDIM / 4;  // 8192
    float s = 0.f, ss = 0.f;
    for (int i = threadIdx.x; i < n4; i += 256) {
        float4 t = xp[i];
        s  += t.x + t.y + t.z + t.w;
        ss += t.x * t.x + t.y * t.y + t.z * t.z + t.w * t.w;
    }
    __shared__ float sh1[8], sh2[8];
    __shared__ float scg[CPG], sbg[CPG];
    int lane = threadIdx.x & 31, wid = threadIdx.x >> 5;
    s = warp_sum(s); ss = warp_sum(ss);
    if (lane == 0) { sh1[wid] = s; sh2[wid] = ss; }
    __syncthreads();
    if (wid == 0) {
        s  = (lane < 8) ? sh1[lane] : 0.f;
        ss = (lane < 8) ? sh2[lane] : 0.f;
        s = warp_sum(s); ss = warp_sum(ss);
        if (lane == 0) { sh1[0] = s; sh2[0] = ss; }
    }
    __syncthreads();
    const float inv_n = 1.f / (float)(CPG * LDIM);
    const float mean = sh1[0] * inv_n;
    const float var  = sh2[0] * inv_n - mean * mean;
    const float rstd = rsqrtf(var + GN_EPS);
    if (threadIdx.x < CPG) {
        float sc = gamma[g * CPG + threadIdx.x] * rstd;
        scg[threadIdx.x] = sc;
        sbg[threadIdx.x] = beta[g * CPG + threadIdx.x] - mean * sc;
    }
    __syncthreads();

    __shared__ float tile[CPG][133];
    for (int l0 = 0; l0 < LDIM; l0 += 128) {
        for (int it = threadIdx.x; it < 512; it += 256) {
            int c  = it >> 5;
            int l4 = (it & 31) * 4;
            float4 t = *reinterpret_cast<const float4*>(&x[base + (size_t)c * LDIM + l0 + l4]);
            float sc = scg[c], sb = sbg[c];
            tile[c][l4 + 0] = t.x * sc + sb;
            tile[c][l4 + 1] = t.y * sc + sb;
            tile[c][l4 + 2] = t.z * sc + sb;
            tile[c][l4 + 3] = t.w * sc + sb;
        }
        __syncthreads();
        for (int it = threadIdx.x; it < 512; it += 256) {
            int l  = it >> 2;
            int c4 = (it & 3) * 4;
            __half2* dst = reinterpret_cast<__half2*>(
                ht + ((size_t)b * LDIM + l0 + l) * CDIM + g * CPG + c4);
            dst[0] = __floats2half2_rn(tile[c4 + 0][l], tile[c4 + 1][l]);
            dst[1] = __floats2half2_rn(tile[c4 + 2][l], tile[c4 + 3][l]);
        }
        __syncthreads();
    }
}

// ============================================================================
// fp16 tensor-core GEMM: D[m,n] = sum_k A[m,k]*B[n,k]  (A:[M,K], B:[N,K] fp16)
// CTA: 128 thr (4 warps), 128x128 tile, warp tile 64x64 (2x2 warp grid).
// K-chunk 64 halves, 3-stage cp.async, XOR swizzle, ldmatrix fragment loads.
// EPI: 0 = fp16 out
//      5 = merged QKU routing: n in [0,512)->q(+bias), [512,1024)->k(+bias2),
//          [1024,1536)->uT transposed, no bias
//      6 = scores: P = fp16(exp(c*alpha - EXP_SHIFT)), atomic row sums -> rsum
//      8 = final: fp32 out = c/rsum[n] + bias[m] + resid[m*ldc+n]
// ============================================================================
#define STAGE_BYTES 32768   // A 16KB + B 16KB
#define GEMM_SMEM   (3 * STAGE_BYTES)

template<int EPI>
__global__ __launch_bounds__(128, 2)
void gemm_h(const __half* __restrict__ A, const __half* __restrict__ B,
            void* __restrict__ Dv, int K, int lda, int ldb, int ldc,
            long long sA, long long sB, long long sD,
            const float* __restrict__ bias, float alpha,
            const float* __restrict__ resid, float* __restrict__ rsum,
            void* __restrict__ Dv2, void* __restrict__ Dv3,
            const float* __restrict__ bias2) {
    extern __shared__ char smem[];
    const uint32_t sb = (uint32_t)__cvta_generic_to_shared(smem);
    const int tid = threadIdx.x;
    const int lane = tid & 31;
    const int warp = tid >> 5;
    const int gid = lane >> 2;   // 0..7
    const int tig = lane & 3;    // 0..3
    const int wm = warp & 1;     // m half
    const int wn = warp >> 1;    // n half
    const int m0 = blockIdx.y * 128;
    const int n0 = blockIdx.x * 128;
    const int bz = blockIdx.z;

    A += (long long)bz * sA;
    B += (long long)bz * sB;

    // ---- cp.async loader geometry: rows lm + u*16, 16B granule lg
    const int lm = tid >> 3;          // 0..15
    const int lg = tid & 7;           // 0..7
    const __half* Ap = A + (long long)(m0 + lm) * lda + lg * 8;
    const __half* Bp = B + (long long)(n0 + lm) * ldb + lg * 8;
    const uint32_t sts_off = (uint32_t)(lm * 128 + (((lg ^ lm) & 7) << 4));

    // ---- ldmatrix geometry
    const int r7 = lane & 7;
    const int lhi = lane >> 4;
    const int arow = ((lane >> 3) & 1) * 8 + r7;
    const int bhi = (lane >> 3) & 1;
    const int brow = ((lane >> 4) & 1) * 8 + r7;
    uint32_t aRowOff[4], bRowOff[4];
#pragma unroll
    for (int mt = 0; mt < 4; mt++)
        aRowOff[mt] = (uint32_t)((wm * 64 + mt * 16 + arow) * 128);
#pragma unroll
    for (int j = 0; j < 4; j++)
        bRowOff[j] = (uint32_t)((wn * 64 + j * 16 + brow) * 128) + 16384u;

    const int nch = K / 64;

#define ISSUE_STAGE(st, buf) do {                                             \
        const uint32_t d0 = sb + (uint32_t)(buf) * STAGE_BYTES + sts_off;     \
        const __half* ap = Ap + (st) * 64;                                    \
        const __half* bp = Bp + (st) * 64;                                    \
        _Pragma("unroll")                                                     \
        for (int u = 0; u < 8; u++)                                           \
            cp_async16(d0 + u * 2048, ap + (long long)u * 16 * lda);          \
        _Pragma("unroll")                                                     \
        for (int u = 0; u < 8; u++)                                           \
            cp_async16(d0 + 16384 + u * 2048, bp + (long long)u * 16 * ldb);  \
    } while (0)

#define LOAD_FRAGS(sl, ks_) do {                                              \
        const uint32_t swa = (uint32_t)((((2 * (ks_) + lhi) ^ r7) & 7) << 4); \
        const uint32_t swb = (uint32_t)((((2 * (ks_) + bhi) ^ r7) & 7) << 4); \
        _Pragma("unroll")                                                     \
        for (int mt = 0; mt < 4; mt++)                                        \
            ldsm_x4(afr[sl][mt][0], afr[sl][mt][1], afr[sl][mt][2],           \
                    afr[sl][mt][3], stage + aRowOff[mt] + swa);               \
        _Pragma("unroll")                                                     \
        for (int j = 0; j < 4; j++)                                           \
            ldsm_x4(bfr[sl][2 * j][0], bfr[sl][2 * j][1],                     \
                    bfr[sl][2 * j + 1][0], bfr[sl][2 * j + 1][1],             \
                    stage + bRowOff[j] + swb);                                \
    } while (0)

    ISSUE_STAGE(0, 0); cp_commit();
    ISSUE_STAGE(1, 1); cp_commit();

    float acc[4][8][4];
#pragma unroll
    for (int i = 0; i < 4; i++)
#pragma unroll
        for (int j = 0; j < 8; j++)
#pragma unroll
            for (int r = 0; r < 4; r++) acc[i][j][r] = 0.f;

    uint32_t afr[2][4][4], bfr[2][8][2];

    for (int i = 0; i < nch; i++) {
        cp_wait<1>();
        __syncthreads();
        if (i + 2 < nch) ISSUE_STAGE(i + 2, (i + 2) % 3);
        cp_commit();

        const uint32_t stage = sb + (uint32_t)(i % 3) * STAGE_BYTES;
        LOAD_FRAGS(0, 0);
#pragma unroll
        for (int ks = 0; ks < 4; ks++) {
            if (ks < 3) LOAD_FRAGS((ks + 1) & 1, ks + 1);
            const int cur = ks & 1;
#pragma unroll
            for (int mt = 0; mt < 4; mt++)
#pragma unroll
                for (int nt = 0; nt < 8; nt++)
                    mma_f16(acc[mt][nt], afr[cur][mt], bfr[cur][nt]);
        }
    }
#undef ISSUE_STAGE
#undef LOAD_FRAGS

    // EPI 8: per-column inverse attention row-sums (n indexes the L axis)
    float invn[8][2];
    if (EPI == 8) {
#pragma unroll
        for (int nt = 0; nt < 8; nt++) {
            const int n = n0 + wn * 64 + nt * 8 + tig * 2;
            invn[nt][0] = 1.f / rsum[(long long)bz * LDIM + n];
            invn[nt][1] = 1.f / rsum[(long long)bz * LDIM + n + 1];
        }
    }

    // epilogue
#pragma unroll
    for (int mt = 0; mt < 4; mt++) {
        const int m = m0 + wm * 64 + mt * 16 + gid;
        float rs0 = 0.f, rs1 = 0.f;            // EPI 6 row-sum partials
#pragma unroll
        for (int nt = 0; nt < 8; nt++) {
            const int n = n0 + wn * 64 + nt * 8 + tig * 2;
            float* c = acc[mt][nt];
            if (EPI == 0) {
                __half* Dh = (__half*)Dv + (long long)bz * sD;
                *reinterpret_cast<__half2*>(Dh + (long long)m * ldc + n) =
                    __floats2half2_rn(c[0], c[1]);
                *reinterpret_cast<__half2*>(Dh + (long long)(m + 8) * ldc + n) =
                    __floats2half2_rn(c[2], c[3]);
            } else if (EPI == 5) {  // merged QKU routing
                const int which = n >> 9;          // 0=q, 1=k, 2=u
                const int nl = n & 511;
                if (which < 2) {
                    __half* Dh = ((which == 0) ? (__half*)Dv : (__half*)Dv2)
                                 + (long long)bz * CL;
                    const float* bb = (which == 0) ? bias : bias2;
                    const float b0v = bb[nl], b1v = bb[nl + 1];
                    *reinterpret_cast<__half2*>(Dh + (long long)m * CDIM + nl) =
                        __floats2half2_rn(c[0] + b0v, c[1] + b1v);
                    *reinterpret_cast<__half2*>(Dh + (long long)(m + 8) * CDIM + nl) =
                        __floats2half2_rn(c[2] + b0v, c[3] + b1v);
                } else {            // u slot: transposed, no bias
                    __half* Dh = (__half*)Dv3 + (long long)bz * CL;
                    Dh[(long long)nl * LDIM + m]           = __float2half(c[0]);
                    Dh[(long long)(nl + 1) * LDIM + m]     = __float2half(c[1]);
                    Dh[(long long)nl * LDIM + m + 8]       = __float2half(c[2]);
                    Dh[(long long)(nl + 1) * LDIM + m + 8] = __float2half(c[3]);
                }
            } else if (EPI == 6) {  // scores -> unnormalized softmax numerator
                __half* Dh = (__half*)Dv + (long long)bz * sD;
                const float e0 = __expf(c[0] * alpha - EXP_SHIFT);
                const float e1 = __expf(c[1] * alpha - EXP_SHIFT);
                const float e2 = __expf(c[2] * alpha - EXP_SHIFT);
                const float e3 = __expf(c[3] * alpha - EXP_SHIFT);
                *reinterpret_cast<__half2*>(Dh + (long long)m * ldc + n) =
                    __floats2half2_rn(e0, e1);
                *reinterpret_cast<__half2*>(Dh + (long long)(m + 8) * ldc + n) =
                    __floats2half2_rn(e2, e3);
                rs0 += e0 + e1;
                rs1 += e2 + e3;
            } else {  // EPI == 8: out = c/rsum[n] + b2[m] + x[m,n]
                float* Df = (float*)Dv + (long long)bz * sD;
                const float* rs = resid + (long long)bz * sD;
                const float bm0 = bias[m], bm1 = bias[m + 8];
                const float2 r0 = *reinterpret_cast<const float2*>(
                    &rs[(long long)m * ldc + n]);
                const float2 r1 = *reinterpret_cast<const float2*>(
                    &rs[(long long)(m + 8) * ldc + n]);
                *reinterpret_cast<float2*>(&Df[(long long)m * ldc + n]) =
                    make_float2(c[0] * invn[nt][0] + bm0 + r0.x,
                                c[1] * invn[nt][1] + bm0 + r0.y);
                *reinterpret_cast<float2*>(&Df[(long long)(m + 8) * ldc + n]) =
                    make_float2(c[2] * invn[nt][0] + bm1 + r1.x,
                                c[3] * invn[nt][1] + bm1 + r1.y);
            }
        }
        if (EPI == 6) {
            rs0 += __shfl_xor_sync(0xFFFFFFFFu, rs0, 1);
            rs0 += __shfl_xor_sync(0xFFFFFFFFu, rs0, 2);
            rs1 += __shfl_xor_sync(0xFFFFFFFFu, rs1, 1);
            rs1 += __shfl_xor_sync(0xFFFFFFFFu, rs1, 2);
            if (tig == 0) {
                atomicAdd(&rsum[(long long)bz * LDIM + m], rs0);
                atomicAdd(&rsum[(long long)bz * LDIM + m + 8], rs1);
            }
        }
    }
}

// ============================================================================
// Launch
// ============================================================================
extern "C" void kernel_launch(void* const* d_in, const int* in_sizes, int n_in,
                              void* d_out, int out_size) {
    (void)in_sizes; (void)n_in; (void)out_size;
    const float* x   = (const float*)d_in[0];
    const float* gns = (const float*)d_in[1];
    const float* gnb = (const float*)d_in[2];
    const float* wq  = (const float*)d_in[3];
    const float* bq  = (const float*)d_in[4];
    const float* wk  = (const float*)d_in[5];
    const float* bk  = (const float*)d_in[6];
    const float* wv  = (const float*)d_in[7];
    const float* bv  = (const float*)d_in[8];
    const float* wo  = (const float*)d_in[9];
    const float* bo  = (const float*)d_in[10];
    float* out = (float*)d_out;

    unsigned char* base = nullptr;
    cudaGetSymbolAddress((void**)&base, g_scratch);
    __half* ht   = (__half*)(base);
    __half* qh   = (__half*)(base + 16777216);
    __half* kh   = (__half*)(base + 33554432);
    __half* uTh  = (__half*)(base + 50331648);
    float*  rsum = (float*)(base + 67108864);
    float*  b2   = (float*)(base + 67174400);
    __half* p    = (__half*)(base + 83886080);
    __half* wh   = (__half*)(base + 150994944);   // [wq | wk | W2]
    __half* wvT  = (__half*)(base + 152567808);
    __half* woh  = (__half*)(base + 153092096);
    __half* w2h  = wh + 524288;                   // slot 2 of wh

    const float attn_scale = 0.044194173824159216f;  // 512^-0.5

    static bool attr_done = false;
    if (!attr_done) {
        cudaFuncSetAttribute(gemm_h<0>, cudaFuncAttributeMaxDynamicSharedMemorySize, GEMM_SMEM);
        cudaFuncSetAttribute(gemm_h<5>, cudaFuncAttributeMaxDynamicSharedMemorySize, GEMM_SMEM);
        cudaFuncSetAttribute(gemm_h<6>, cudaFuncAttributeMaxDynamicSharedMemorySize, GEMM_SMEM);
        cudaFuncSetAttribute(gemm_h<8>, cudaFuncAttributeMaxDynamicSharedMemorySize, GEMM_SMEM);
        attr_done = true;
    }

    // 0) Weights -> fp16 (wq, wk, wvT, wo) + zero rsum; b2 = Wo@bv + bo
    conv_w_kernel<<<4096, 256>>>(wq, wk, wv, wo, wh, wvT, woh, rsum);
    bias2_kernel<<<64, 256>>>(wo, bv, bo, b2);

    // 1) W2 = Wo @ Wv  (fp16, 512x512x512): D[o,e] = sum_c woh[o,c]*wvT[e,c]
    {
        dim3 grid(4, 4, 1);
        gemm_h<0><<<grid, 128, GEMM_SMEM>>>(woh, wvT, w2h, CDIM, CDIM, CDIM, CDIM,
            0, 0, 0, nullptr, 0.f, nullptr, nullptr, nullptr, nullptr, nullptr);
    }

    // 2) GroupNorm + transpose: ht [B, L, C] fp16
    gn_t_kernel<<<BDIM * NGRP, 256>>>(x, gns, gnb, ht);

    // 3) Merged QKU projection: M=L, N=3C=1536, K=C
    //    q = ht@wq^T + bq, k = ht@wk^T + bk, uT = (ht@W2^T)^T (no bias)
    {
        dim3 grid(1536 / 128, LDIM / 128, BDIM);
        gemm_h<5><<<grid, 128, GEMM_SMEM>>>(ht, wh, qh, CDIM, CDIM, CDIM, CDIM,
            CL, 0, CL, bq, 0.f, nullptr, nullptr, kh, uTh, bk);
    }

    // 4) Scores fused with exp: p[i,j] = fp16(exp(scale*q.k - 4)), rsum[i] += ...
    {
        dim3 grid(LDIM / 128, LDIM / 128, BDIM);
        gemm_h<6><<<grid, 128, GEMM_SMEM>>>(qh, kh, p, CDIM, CDIM, CDIM, LDIM,
            CL, CL, LL, nullptr, attn_scale, nullptr, rsum, nullptr, nullptr,
            nullptr);
    }

    // 5) Final: out[o,l] = sum_j p[l,j]*uT[o,j] / rsum[l] + b2[o] + x[o,l]
    //    M=C(rows o), N=L(cols l), K=L(j). A=uT [C,L], B=p [L,L].
    {
        dim3 grid(LDIM / 128, CDIM / 128, BDIM);
        gemm_h<8><<<grid, 128, GEMM_SMEM>>>(uTh, p, out, LDIM, LDIM, LDIM, LDIM,
            CL, LL, CL, b2, 0.f, x, rsum, nullptr, nullptr, nullptr);
    }
}